// round 1
// baseline (speedup 1.0000x reference)
#include <cuda_runtime.h>
#include <math.h>

// Problem constants
#define DIMN 2048
#define HN   16
#define KVHN 4
#define HDN  128
#define RDN  64
#define BN_  4
#define TN_  2048
#define QK_SCALE 0.08838834764831845f   // 128^-0.5
#define EPS_RMS  1e-6f
#define EPS_NORM 1e-12f

// Scratch (allocation-free rule: __device__ globals)
__device__ float g_q[(size_t)BN_ * TN_ * DIMN];        // [b,t,h*128+d]
__device__ float g_k[(size_t)BN_ * TN_ * KVHN * HDN];  // [b,t,kvh*128+d]
__device__ float g_v[(size_t)BN_ * TN_ * KVHN * HDN];
__device__ float g_y[(size_t)BN_ * TN_ * DIMN];

// ---------------------------------------------------------------------------
// SGEMM: C[m,n] = sum_k A[m,k] * B[n,k]   (A: MxK row-major, B: NxK row-major)
// 128x128 tile, BK=8, 256 threads, 8x8 per-thread microtile.
// ---------------------------------------------------------------------------
__global__ __launch_bounds__(256) void sgemm_nt(
    const float* __restrict__ A, const float* __restrict__ B,
    float* __restrict__ C, int M, int N, int K)
{
    __shared__ float As[8][128];
    __shared__ float Bs[8][128];

    const int tid = threadIdx.x;
    const int bm = blockIdx.y * 128;
    const int bn = blockIdx.x * 128;
    const int tx = tid & 15;   // 0..15
    const int ty = tid >> 4;   // 0..15

    float acc[8][8];
#pragma unroll
    for (int i = 0; i < 8; i++)
#pragma unroll
        for (int j = 0; j < 8; j++) acc[i][j] = 0.f;

    const int lrow = tid >> 1;          // 0..127
    const int lcol = (tid & 1) * 4;     // 0 or 4
    const float* Ap = A + (size_t)(bm + lrow) * K + lcol;
    const float* Bp = B + (size_t)(bn + lrow) * K + lcol;

    for (int k0 = 0; k0 < K; k0 += 8) {
        float4 a = *(const float4*)(Ap + k0);
        float4 b = *(const float4*)(Bp + k0);
        __syncthreads();  // previous iteration's compute done before smem overwrite
        As[lcol + 0][lrow] = a.x; As[lcol + 1][lrow] = a.y;
        As[lcol + 2][lrow] = a.z; As[lcol + 3][lrow] = a.w;
        Bs[lcol + 0][lrow] = b.x; Bs[lcol + 1][lrow] = b.y;
        Bs[lcol + 2][lrow] = b.z; Bs[lcol + 3][lrow] = b.w;
        __syncthreads();
#pragma unroll
        for (int kk = 0; kk < 8; kk++) {
            float4 a0 = *(const float4*)&As[kk][ty * 8];
            float4 a1 = *(const float4*)&As[kk][ty * 8 + 4];
            float4 b0 = *(const float4*)&Bs[kk][tx * 8];
            float4 b1 = *(const float4*)&Bs[kk][tx * 8 + 4];
            float ra[8] = {a0.x, a0.y, a0.z, a0.w, a1.x, a1.y, a1.z, a1.w};
            float rb[8] = {b0.x, b0.y, b0.z, b0.w, b1.x, b1.y, b1.z, b1.w};
#pragma unroll
            for (int i = 0; i < 8; i++)
#pragma unroll
                for (int j = 0; j < 8; j++)
                    acc[i][j] += ra[i] * rb[j];
        }
    }

#pragma unroll
    for (int i = 0; i < 8; i++) {
        int row = bm + ty * 8 + i;
        float4 o0 = make_float4(acc[i][0], acc[i][1], acc[i][2], acc[i][3]);
        float4 o1 = make_float4(acc[i][4], acc[i][5], acc[i][6], acc[i][7]);
        *(float4*)(C + (size_t)row * N + bn + tx * 8)     = o0;
        *(float4*)(C + (size_t)row * N + bn + tx * 8 + 4) = o1;
    }
}

// ---------------------------------------------------------------------------
// RMSNorm + RoPE (+ q_gain) applied in place to q heads (16) and k heads (4).
// One warp per (b*T+t, head) row of 128 floats.
// ---------------------------------------------------------------------------
__global__ __launch_bounds__(256) void norm_rope_kernel(const float* __restrict__ qgain)
{
    const int gw   = (blockIdx.x * blockDim.x + threadIdx.x) >> 5;
    const int lane = threadIdx.x & 31;
    const int total = BN_ * TN_ * (HN + KVHN);
    if (gw >= total) return;

    const int head = gw % (HN + KVHN);
    const int row  = gw / (HN + KVHN);   // b*T + t
    const int t    = row % TN_;

    float* ptr;
    float gain = 1.f;
    if (head < HN) {
        ptr = g_q + (size_t)row * DIMN + head * HDN;
        gain = qgain[head];
    } else {
        ptr = g_k + (size_t)row * (KVHN * HDN) + (head - HN) * HDN;
    }

    float4 v = *(const float4*)(ptr + lane * 4);
    float ss = v.x * v.x + v.y * v.y + v.z * v.z + v.w * v.w;
#pragma unroll
    for (int o = 16; o; o >>= 1) ss += __shfl_xor_sync(0xffffffffu, ss, o);
    const float r = rsqrtf(ss * (1.f / 128.f) + EPS_RMS);
    v.x *= r; v.y *= r; v.z *= r; v.w *= r;

    // RoPE on dims [0,64): lanes 0..7 hold x1 (dims 0..31), lanes 8..15 hold x2.
    float4 p;
    p.x = __shfl_xor_sync(0xffffffffu, v.x, 8);
    p.y = __shfl_xor_sync(0xffffffffu, v.y, 8);
    p.z = __shfl_xor_sync(0xffffffffu, v.z, 8);
    p.w = __shfl_xor_sync(0xffffffffu, v.w, 8);

    if (lane < 16) {
        const int base = (lane & 7) * 4;   // j index within [0,32)
        float* ve = &v.x;
        const float* pe = &p.x;
#pragma unroll
        for (int e = 0; e < 4; e++) {
            const int j = base + e;
            const float inv = powf(10000.f, -(float)j / 32.f);
            float s, c;
            sincosf((float)t * inv, &s, &c);
            if (lane < 8) {
                // x1*cos - x2*sin
                ve[e] = ve[e] * c - pe[e] * s;
            } else {
                // x2*cos + x1*sin
                ve[e] = ve[e] * c + pe[e] * s;
            }
        }
    }
    v.x *= gain; v.y *= gain; v.z *= gain; v.w *= gain;
    *(float4*)(ptr + lane * 4) = v;
}

// ---------------------------------------------------------------------------
// Causal GQA flash attention + v-orthogonalization epilogue.
// Block = 8 warps, each warp owns one query row t (same b,h for the block).
// Key/value staged in smem in 32-key tiles shared by all 8 warps.
// ---------------------------------------------------------------------------
__global__ __launch_bounds__(256) void attn_kernel()
{
    __shared__ float ks[32][132];
    __shared__ float vs[32][132];
    __shared__ float qs[8][132];

    const int bh   = blockIdx.y;
    const int b    = bh / HN;
    const int h    = bh % HN;
    const int kvh  = h / (HN / KVHN);
    const int t0   = blockIdx.x * 8;
    const int warp = threadIdx.x >> 5;
    const int lane = threadIdx.x & 31;
    const int t    = t0 + warp;

    // stage q rows
    {
        const float* qp = g_q + ((size_t)(b * TN_ + t)) * DIMN + h * HDN;
        *(float4*)&qs[warp][lane * 4] = *(const float4*)(qp + lane * 4);
    }

    float a0 = 0.f, a1 = 0.f, a2 = 0.f, a3 = 0.f;
    float m = -INFINITY, l = 0.f;

    const int t_max = t0 + 7;
    const int nkb = (t_max >> 5) + 1;

    for (int kb = 0; kb < nkb; kb++) {
        const int j0 = kb * 32;
        __syncthreads();
        // cooperative k/v tile load: 32 keys x 128 floats each
#pragma unroll
        for (int r = 0; r < 4; r++) {
            const int idx = r * 256 + threadIdx.x;  // 0..1023
            const int key = idx >> 5;
            const int c4  = idx & 31;
            const size_t gbase = ((size_t)(b * TN_ + j0 + key)) * (KVHN * HDN) + kvh * HDN + c4 * 4;
            *(float4*)&ks[key][c4 * 4] = *(const float4*)(g_k + gbase);
            *(float4*)&vs[key][c4 * 4] = *(const float4*)(g_v + gbase);
        }
        __syncthreads();

        if (j0 > t) continue;  // fully masked tile for this warp

        const int j = j0 + lane;
        float s;
        if (j <= t) {
            s = 0.f;
#pragma unroll
            for (int c4 = 0; c4 < 32; c4++) {
                float4 kk = *(const float4*)&ks[lane][c4 * 4];
                float4 qq = *(const float4*)&qs[warp][c4 * 4];
                s += qq.x * kk.x + qq.y * kk.y + qq.z * kk.z + qq.w * kk.w;
            }
            s *= QK_SCALE;
        } else {
            s = -INFINITY;
        }

        float smax = s;
#pragma unroll
        for (int o = 16; o; o >>= 1)
            smax = fmaxf(smax, __shfl_xor_sync(0xffffffffu, smax, o));
        const float mnew = fmaxf(m, smax);
        const float corr = __expf(m - mnew);     // exp(-inf)=0 on first tile
        float pp = (j <= t) ? __expf(s - mnew) : 0.f;
        float psum = pp;
#pragma unroll
        for (int o = 16; o; o >>= 1) psum += __shfl_xor_sync(0xffffffffu, psum, o);
        l = l * corr + psum;
        a0 *= corr; a1 *= corr; a2 *= corr; a3 *= corr;
        m = mnew;

        // O[d] += sum_j p_j * v[j][d]; lane owns d = lane*4 .. lane*4+3
#pragma unroll
        for (int jj = 0; jj < 32; jj++) {
            const float pj = __shfl_sync(0xffffffffu, pp, jj);
            float4 vv = *(const float4*)&vs[jj][lane * 4];
            a0 += pj * vv.x; a1 += pj * vv.y; a2 += pj * vv.z; a3 += pj * vv.w;
        }
    }

    const float inv_l = 1.f / l;
    a0 *= inv_l; a1 *= inv_l; a2 *= inv_l; a3 *= inv_l;

    // v-orthogonalization: vhat = v[b,kvh,t]/max(||v||,eps); y -= (y.vhat)*vhat
    const float* vp = g_v + ((size_t)(b * TN_ + t)) * (KVHN * HDN) + kvh * HDN;
    float4 vt = *(const float4*)(vp + lane * 4);
    float nn = vt.x * vt.x + vt.y * vt.y + vt.z * vt.z + vt.w * vt.w;
#pragma unroll
    for (int o = 16; o; o >>= 1) nn += __shfl_xor_sync(0xffffffffu, nn, o);
    const float invn = 1.f / fmaxf(sqrtf(nn), EPS_NORM);
    float dotv = a0 * vt.x + a1 * vt.y + a2 * vt.z + a3 * vt.w;  // y . v
#pragma unroll
    for (int o = 16; o; o >>= 1) dotv += __shfl_xor_sync(0xffffffffu, dotv, o);
    const float cfac = dotv * invn * invn;
    a0 -= cfac * vt.x; a1 -= cfac * vt.y; a2 -= cfac * vt.z; a3 -= cfac * vt.w;

    float* yp = g_y + ((size_t)(b * TN_ + t)) * DIMN + h * HDN;
    *(float4*)(yp + lane * 4) = make_float4(a0, a1, a2, a3);
}

// ---------------------------------------------------------------------------
// Launch
// ---------------------------------------------------------------------------
extern "C" void kernel_launch(void* const* d_in, const int* in_sizes, int n_in,
                              void* d_out, int out_size)
{
    const float* x     = (const float*)d_in[0];   // (4,2048,2048)
    const float* Wq    = (const float*)d_in[1];   // (2048,2048)
    const float* Wk    = (const float*)d_in[2];   // (512,2048)
    const float* Wv    = (const float*)d_in[3];   // (512,2048)
    const float* Wproj = (const float*)d_in[4];   // (2048,2048)
    const float* qgain = (const float*)d_in[5];   // (16,)
    float* out = (float*)d_out;

    float *q_ptr, *k_ptr, *v_ptr, *y_ptr;
    cudaGetSymbolAddress((void**)&q_ptr, g_q);
    cudaGetSymbolAddress((void**)&k_ptr, g_k);
    cudaGetSymbolAddress((void**)&v_ptr, g_v);
    cudaGetSymbolAddress((void**)&y_ptr, g_y);

    const int M = BN_ * TN_;   // 8192

    // QKV projections
    sgemm_nt<<<dim3(DIMN / 128, M / 128), 256>>>(x, Wq, q_ptr, M, DIMN, DIMN);
    sgemm_nt<<<dim3((KVHN * HDN) / 128, M / 128), 256>>>(x, Wk, k_ptr, M, KVHN * HDN, DIMN);
    sgemm_nt<<<dim3((KVHN * HDN) / 128, M / 128), 256>>>(x, Wv, v_ptr, M, KVHN * HDN, DIMN);

    // RMSNorm + RoPE (+gain) on q and k heads
    {
        const int total_warps = M * (HN + KVHN);
        const int threads = 256;
        const int blocks = (total_warps * 32 + threads - 1) / threads;
        norm_rope_kernel<<<blocks, threads>>>(qgain);
    }

    // Causal GQA attention + v-orthogonalization
    attn_kernel<<<dim3(TN_ / 8, BN_ * HN), 256>>>();

    // Output projection
    sgemm_nt<<<dim3(DIMN / 128, M / 128), 256>>>(y_ptr, Wproj, out, M, DIMN, DIMN);
}

// round 3
// speedup vs baseline: 1.4332x; 1.4332x over previous
#include <cuda_runtime.h>
#include <cuda_bf16.h>
#include <math.h>

// Problem constants
#define DIMN 2048
#define HN   16
#define KVHN 4
#define HDN  128
#define BN_  4
#define TN_  2048
#define QK_SCALE 0.08838834764831845f   // 128^-0.5
#define EPS_RMS  1e-6f
#define EPS_NORM 1e-12f

// ---------------------------------------------------------------------------
// Scratch (__device__ globals: allocation-free rule)
// ---------------------------------------------------------------------------
__device__ __align__(256) float g_q[(size_t)BN_ * TN_ * DIMN];
__device__ __align__(256) float g_k[(size_t)BN_ * TN_ * KVHN * HDN];
__device__ __align__(256) float g_v[(size_t)BN_ * TN_ * KVHN * HDN];
__device__ __align__(256) float g_y[(size_t)BN_ * TN_ * DIMN];

__device__ __align__(256) __nv_bfloat16 g_xhi[(size_t)BN_ * TN_ * DIMN];
__device__ __align__(256) __nv_bfloat16 g_xlo[(size_t)BN_ * TN_ * DIMN];
__device__ __align__(256) __nv_bfloat16 g_yhi[(size_t)BN_ * TN_ * DIMN];
__device__ __align__(256) __nv_bfloat16 g_ylo[(size_t)BN_ * TN_ * DIMN];
__device__ __align__(256) __nv_bfloat16 g_wqhi[(size_t)DIMN * DIMN];
__device__ __align__(256) __nv_bfloat16 g_wqlo[(size_t)DIMN * DIMN];
__device__ __align__(256) __nv_bfloat16 g_wphi[(size_t)DIMN * DIMN];
__device__ __align__(256) __nv_bfloat16 g_wplo[(size_t)DIMN * DIMN];
__device__ __align__(256) __nv_bfloat16 g_wkhi[(size_t)KVHN * HDN * DIMN];
__device__ __align__(256) __nv_bfloat16 g_wklo[(size_t)KVHN * HDN * DIMN];
__device__ __align__(256) __nv_bfloat16 g_wvhi[(size_t)KVHN * HDN * DIMN];
__device__ __align__(256) __nv_bfloat16 g_wvlo[(size_t)KVHN * HDN * DIMN];

// ---------------------------------------------------------------------------
// Helpers
// ---------------------------------------------------------------------------
__device__ __forceinline__ unsigned smem_u32(const void* p) {
    unsigned a;
    asm("{ .reg .u64 t; cvta.to.shared.u64 t, %1; cvt.u32.u64 %0, t; }"
        : "=r"(a) : "l"(p));
    return a;
}
__device__ __forceinline__ void cp16(unsigned saddr, const void* gaddr) {
    asm volatile("cp.async.cg.shared.global [%0], [%1], 16;"
                 :: "r"(saddr), "l"(gaddr));
}
__device__ __forceinline__ void cp_commit() {
    asm volatile("cp.async.commit_group;" ::: "memory");
}
__device__ __forceinline__ void cp_wait1() {
    asm volatile("cp.async.wait_group 1;" ::: "memory");
}
__device__ __forceinline__ void cp_wait0() {
    asm volatile("cp.async.wait_group 0;" ::: "memory");
}
__device__ __forceinline__ void ldsm_x4(unsigned addr, unsigned* r) {
    asm volatile("ldmatrix.sync.aligned.m8n8.x4.shared.b16 {%0,%1,%2,%3}, [%4];"
                 : "=r"(r[0]), "=r"(r[1]), "=r"(r[2]), "=r"(r[3]) : "r"(addr));
}
__device__ __forceinline__ void mma_bf16(float* d, const unsigned* a,
                                         const unsigned* b) {
    asm volatile(
        "mma.sync.aligned.m16n8k16.row.col.f32.bf16.bf16.f32 "
        "{%0,%1,%2,%3}, {%4,%5,%6,%7}, {%8,%9}, {%0,%1,%2,%3};"
        : "+f"(d[0]), "+f"(d[1]), "+f"(d[2]), "+f"(d[3])
        : "r"(a[0]), "r"(a[1]), "r"(a[2]), "r"(a[3]), "r"(b[0]), "r"(b[1]));
}

// ---------------------------------------------------------------------------
// Split fp32 -> (bf16 hi, bf16 lo)
// ---------------------------------------------------------------------------
__global__ __launch_bounds__(256) void split_kernel(
    const float* __restrict__ s, __nv_bfloat16* __restrict__ hi,
    __nv_bfloat16* __restrict__ lo, int n)
{
    int i = (blockIdx.x * 256 + threadIdx.x) * 4;
    if (i >= n) return;
    float4 v = *(const float4*)(s + i);
    float vv[4] = {v.x, v.y, v.z, v.w};
    __nv_bfloat16 h[4], l[4];
#pragma unroll
    for (int e = 0; e < 4; e++) {
        h[e] = __float2bfloat16(vv[e]);
        l[e] = __float2bfloat16(vv[e] - __bfloat162float(h[e]));
    }
    *(uint2*)(hi + i) = *(uint2*)h;
    *(uint2*)(lo + i) = *(uint2*)l;
}

// ---------------------------------------------------------------------------
// mma.sync bf16 split-3 GEMM: C[m,n] = sum_k A[m,k]*B[n,k]
// A:[M,K], B:[N,K] row-major (hi/lo pairs). CTA 128x128xBK64, 8 warps (4Mx2N),
// warp tile 32x64. cp.async double buffer, SW128-style swizzle, ldmatrix.
// ---------------------------------------------------------------------------
#define TILE_SZ   16384          // 128 rows x 128 bytes
#define STAGE_SZ  (4 * TILE_SZ)  // Ahi, Alo, Bhi, Blo
#define GEMM_SMEM (2 * STAGE_SZ) // 131072

__global__ __launch_bounds__(256, 1) void gemm_mma_bf16x3(
    const __nv_bfloat16* __restrict__ Ahi, const __nv_bfloat16* __restrict__ Alo,
    const __nv_bfloat16* __restrict__ Bhi, const __nv_bfloat16* __restrict__ Blo,
    float* __restrict__ C, int M, int N, int K)
{
    extern __shared__ char smem[];
    const unsigned sb = smem_u32(smem);
    const int tid  = threadIdx.x;
    const int wid  = tid >> 5;
    const int lane = tid & 31;
    const int wm   = wid & 3;    // 0..3 -> M offset wm*32
    const int wn   = wid >> 2;   // 0..1 -> N offset wn*64
    const int bm   = blockIdx.y * 128;
    const int bn   = blockIdx.x * 128;

    const __nv_bfloat16* tsrc[4] = {Ahi, Alo, Bhi, Blo};
    const int tbase[4] = {bm, bm, bn, bn};

    // stage loader: chunk c (64 k-elems) into buffer buf
    auto stage_load = [&](int c, int buf) {
#pragma unroll
        for (int t = 0; t < 4; t++) {
            const __nv_bfloat16* src = tsrc[t];
            const int rb = tbase[t];
#pragma unroll
            for (int part = 0; part < 4; part++) {
                int idx = part * 256 + tid;      // 0..1023
                int r   = idx >> 3;              // 0..127
                int ch  = idx & 7;               // 16B chunk
                const void* g = src + (size_t)(rb + r) * K + c * 64 + ch * 8;
                unsigned so = sb + buf * STAGE_SZ + t * TILE_SZ
                            + r * 128 + ((ch ^ (r & 7)) * 16);
                cp16(so, g);
            }
        }
    };

    float acc[2][8][4];
#pragma unroll
    for (int mi = 0; mi < 2; mi++)
#pragma unroll
        for (int ni = 0; ni < 8; ni++)
#pragma unroll
            for (int e = 0; e < 4; e++) acc[mi][ni][e] = 0.f;

    const int nK = K >> 6;
    stage_load(0, 0);
    cp_commit();

    for (int c = 0; c < nK; c++) {
        const int buf = c & 1;
        if (c + 1 < nK) {
            stage_load(c + 1, buf ^ 1);
            cp_commit();
            cp_wait1();
        } else {
            cp_wait0();
        }
        __syncthreads();

        const unsigned base = sb + buf * STAGE_SZ;
#pragma unroll
        for (int s = 0; s < 4; s++) {
            // A fragments (hi & lo) : 2 m16 frags
            unsigned a_hi[2][4], a_lo[2][4];
#pragma unroll
            for (int mi = 0; mi < 2; mi++) {
                int r  = wm * 32 + mi * 16 + (lane & 15);
                int ch = 2 * s + (lane >> 4);
                unsigned ad = base + r * 128 + ((ch ^ (r & 7)) * 16);
                ldsm_x4(ad, a_hi[mi]);
                ldsm_x4(ad + TILE_SZ, a_lo[mi]);
            }
            // B fragments (hi & lo): 4 n16 groups -> 8 n8 frags
            unsigned b_hi[4][4], b_lo[4][4];
#pragma unroll
            for (int gi = 0; gi < 4; gi++) {
                int r  = wn * 64 + gi * 16 + (lane & 7) + ((lane >> 4) & 1) * 8;
                int ch = 2 * s + ((lane >> 3) & 1);
                unsigned ad = base + 2 * TILE_SZ + r * 128 + ((ch ^ (r & 7)) * 16);
                ldsm_x4(ad, b_hi[gi]);
                ldsm_x4(ad + TILE_SZ, b_lo[gi]);
            }
            // 16 logical mma x 3 split terms
#pragma unroll
            for (int mi = 0; mi < 2; mi++) {
#pragma unroll
                for (int ni = 0; ni < 8; ni++) {
                    const unsigned bh[2] = {b_hi[ni >> 1][(ni & 1) * 2],
                                            b_hi[ni >> 1][(ni & 1) * 2 + 1]};
                    const unsigned bl[2] = {b_lo[ni >> 1][(ni & 1) * 2],
                                            b_lo[ni >> 1][(ni & 1) * 2 + 1]};
                    mma_bf16(acc[mi][ni], a_hi[mi], bh);
                    mma_bf16(acc[mi][ni], a_lo[mi], bh);
                    mma_bf16(acc[mi][ni], a_hi[mi], bl);
                }
            }
        }
        __syncthreads();
    }

    // Epilogue: direct fp32 stores
#pragma unroll
    for (int mi = 0; mi < 2; mi++) {
#pragma unroll
        for (int ni = 0; ni < 8; ni++) {
            int row = bm + wm * 32 + mi * 16 + (lane >> 2);
            int col = bn + wn * 64 + ni * 8 + (lane & 3) * 2;
            *(float2*)(C + (size_t)row * N + col) =
                make_float2(acc[mi][ni][0], acc[mi][ni][1]);
            *(float2*)(C + (size_t)(row + 8) * N + col) =
                make_float2(acc[mi][ni][2], acc[mi][ni][3]);
        }
    }
}

// ---------------------------------------------------------------------------
// RMSNorm + RoPE (+ q_gain), one warp per (row, head)
// ---------------------------------------------------------------------------
__global__ __launch_bounds__(256) void norm_rope_kernel(const float* __restrict__ qgain)
{
    const int gw   = (blockIdx.x * blockDim.x + threadIdx.x) >> 5;
    const int lane = threadIdx.x & 31;
    const int total = BN_ * TN_ * (HN + KVHN);
    if (gw >= total) return;

    const int head = gw % (HN + KVHN);
    const int row  = gw / (HN + KVHN);
    const int t    = row % TN_;

    float* ptr;
    float gain = 1.f;
    if (head < HN) {
        ptr = g_q + (size_t)row * DIMN + head * HDN;
        gain = qgain[head];
    } else {
        ptr = g_k + (size_t)row * (KVHN * HDN) + (head - HN) * HDN;
    }

    float4 v = *(const float4*)(ptr + lane * 4);
    float ss = v.x * v.x + v.y * v.y + v.z * v.z + v.w * v.w;
#pragma unroll
    for (int o = 16; o; o >>= 1) ss += __shfl_xor_sync(0xffffffffu, ss, o);
    const float r = rsqrtf(ss * (1.f / 128.f) + EPS_RMS);
    v.x *= r; v.y *= r; v.z *= r; v.w *= r;

    float4 p;
    p.x = __shfl_xor_sync(0xffffffffu, v.x, 8);
    p.y = __shfl_xor_sync(0xffffffffu, v.y, 8);
    p.z = __shfl_xor_sync(0xffffffffu, v.z, 8);
    p.w = __shfl_xor_sync(0xffffffffu, v.w, 8);

    if (lane < 16) {
        const int base = (lane & 7) * 4;
        float* ve = &v.x;
        const float* pe = &p.x;
#pragma unroll
        for (int e = 0; e < 4; e++) {
            const int j = base + e;
            const float inv = powf(10000.f, -(float)j / 32.f);
            float s, c;
            sincosf((float)t * inv, &s, &c);
            if (lane < 8) ve[e] = ve[e] * c - pe[e] * s;
            else          ve[e] = ve[e] * c + pe[e] * s;
        }
    }
    v.x *= gain; v.y *= gain; v.z *= gain; v.w *= gain;
    *(float4*)(ptr + lane * 4) = v;
}

// ---------------------------------------------------------------------------
// Causal GQA flash attention + v-orthogonalization (fp32, unchanged)
// ---------------------------------------------------------------------------
__global__ __launch_bounds__(256) void attn_kernel()
{
    __shared__ float ks[32][132];
    __shared__ float vs[32][132];
    __shared__ float qs[8][132];

    const int bh   = blockIdx.y;
    const int b    = bh / HN;
    const int h    = bh % HN;
    const int kvh  = h / (HN / KVHN);
    const int t0   = blockIdx.x * 8;
    const int warp = threadIdx.x >> 5;
    const int lane = threadIdx.x & 31;
    const int t    = t0 + warp;

    {
        const float* qp = g_q + ((size_t)(b * TN_ + t)) * DIMN + h * HDN;
        *(float4*)&qs[warp][lane * 4] = *(const float4*)(qp + lane * 4);
    }

    float a0 = 0.f, a1 = 0.f, a2 = 0.f, a3 = 0.f;
    float m = -INFINITY, l = 0.f;

    const int t_max = t0 + 7;
    const int nkb = (t_max >> 5) + 1;

    for (int kb = 0; kb < nkb; kb++) {
        const int j0 = kb * 32;
        __syncthreads();
#pragma unroll
        for (int r = 0; r < 4; r++) {
            const int idx = r * 256 + threadIdx.x;
            const int key = idx >> 5;
            const int c4  = idx & 31;
            const size_t gbase = ((size_t)(b * TN_ + j0 + key)) * (KVHN * HDN) + kvh * HDN + c4 * 4;
            *(float4*)&ks[key][c4 * 4] = *(const float4*)(g_k + gbase);
            *(float4*)&vs[key][c4 * 4] = *(const float4*)(g_v + gbase);
        }
        __syncthreads();

        if (j0 > t) continue;

        const int j = j0 + lane;
        float s;
        if (j <= t) {
            s = 0.f;
#pragma unroll
            for (int c4 = 0; c4 < 32; c4++) {
                float4 kk = *(const float4*)&ks[lane][c4 * 4];
                float4 qq = *(const float4*)&qs[warp][c4 * 4];
                s += qq.x * kk.x + qq.y * kk.y + qq.z * kk.z + qq.w * kk.w;
            }
            s *= QK_SCALE;
        } else {
            s = -INFINITY;
        }

        float smax = s;
#pragma unroll
        for (int o = 16; o; o >>= 1)
            smax = fmaxf(smax, __shfl_xor_sync(0xffffffffu, smax, o));
        const float mnew = fmaxf(m, smax);
        const float corr = __expf(m - mnew);
        float pp = (j <= t) ? __expf(s - mnew) : 0.f;
        float psum = pp;
#pragma unroll
        for (int o = 16; o; o >>= 1) psum += __shfl_xor_sync(0xffffffffu, psum, o);
        l = l * corr + psum;
        a0 *= corr; a1 *= corr; a2 *= corr; a3 *= corr;
        m = mnew;

#pragma unroll
        for (int jj = 0; jj < 32; jj++) {
            const float pj = __shfl_sync(0xffffffffu, pp, jj);
            float4 vv = *(const float4*)&vs[jj][lane * 4];
            a0 += pj * vv.x; a1 += pj * vv.y; a2 += pj * vv.z; a3 += pj * vv.w;
        }
    }

    const float inv_l = 1.f / l;
    a0 *= inv_l; a1 *= inv_l; a2 *= inv_l; a3 *= inv_l;

    const float* vp = g_v + ((size_t)(b * TN_ + t)) * (KVHN * HDN) + kvh * HDN;
    float4 vt = *(const float4*)(vp + lane * 4);
    float nn = vt.x * vt.x + vt.y * vt.y + vt.z * vt.z + vt.w * vt.w;
#pragma unroll
    for (int o = 16; o; o >>= 1) nn += __shfl_xor_sync(0xffffffffu, nn, o);
    const float invn = 1.f / fmaxf(sqrtf(nn), EPS_NORM);
    float dotv = a0 * vt.x + a1 * vt.y + a2 * vt.z + a3 * vt.w;
#pragma unroll
    for (int o = 16; o; o >>= 1) dotv += __shfl_xor_sync(0xffffffffu, dotv, o);
    const float cfac = dotv * invn * invn;
    a0 -= cfac * vt.x; a1 -= cfac * vt.y; a2 -= cfac * vt.z; a3 -= cfac * vt.w;

    float* yp = g_y + ((size_t)(b * TN_ + t)) * DIMN + h * HDN;
    *(float4*)(yp + lane * 4) = make_float4(a0, a1, a2, a3);
}

// ---------------------------------------------------------------------------
// Launch
// ---------------------------------------------------------------------------
extern "C" void kernel_launch(void* const* d_in, const int* in_sizes, int n_in,
                              void* d_out, int out_size)
{
    const float* x     = (const float*)d_in[0];
    const float* Wq    = (const float*)d_in[1];
    const float* Wk    = (const float*)d_in[2];
    const float* Wv    = (const float*)d_in[3];
    const float* Wproj = (const float*)d_in[4];
    const float* qgain = (const float*)d_in[5];
    float* out = (float*)d_out;

    float *q_ptr, *k_ptr, *v_ptr, *y_ptr;
    cudaGetSymbolAddress((void**)&q_ptr, g_q);
    cudaGetSymbolAddress((void**)&k_ptr, g_k);
    cudaGetSymbolAddress((void**)&v_ptr, g_v);
    cudaGetSymbolAddress((void**)&y_ptr, g_y);
    __nv_bfloat16 *xhi, *xlo, *yhi, *ylo, *wqhi, *wqlo, *wkhi, *wklo, *wvhi, *wvlo, *wphi, *wplo;
    cudaGetSymbolAddress((void**)&xhi, g_xhi);   cudaGetSymbolAddress((void**)&xlo, g_xlo);
    cudaGetSymbolAddress((void**)&yhi, g_yhi);   cudaGetSymbolAddress((void**)&ylo, g_ylo);
    cudaGetSymbolAddress((void**)&wqhi, g_wqhi); cudaGetSymbolAddress((void**)&wqlo, g_wqlo);
    cudaGetSymbolAddress((void**)&wkhi, g_wkhi); cudaGetSymbolAddress((void**)&wklo, g_wklo);
    cudaGetSymbolAddress((void**)&wvhi, g_wvhi); cudaGetSymbolAddress((void**)&wvlo, g_wvlo);
    cudaGetSymbolAddress((void**)&wphi, g_wphi); cudaGetSymbolAddress((void**)&wplo, g_wplo);

    cudaFuncSetAttribute(gemm_mma_bf16x3, cudaFuncAttributeMaxDynamicSharedMemorySize, GEMM_SMEM);

    const int M = BN_ * TN_;            // 8192
    const int NKV = KVHN * HDN;         // 512

    // Split inputs / weights to bf16 hi+lo
    split_kernel<<<(M * DIMN) / 1024, 256>>>(x, xhi, xlo, M * DIMN);
    split_kernel<<<(DIMN * DIMN) / 1024, 256>>>(Wq, wqhi, wqlo, DIMN * DIMN);
    split_kernel<<<(NKV * DIMN) / 1024, 256>>>(Wk, wkhi, wklo, NKV * DIMN);
    split_kernel<<<(NKV * DIMN) / 1024, 256>>>(Wv, wvhi, wvlo, NKV * DIMN);
    split_kernel<<<(DIMN * DIMN) / 1024, 256>>>(Wproj, wphi, wplo, DIMN * DIMN);

    // QKV projections (mma.sync bf16 split-3)
    gemm_mma_bf16x3<<<dim3(DIMN / 128, M / 128), 256, GEMM_SMEM>>>(
        xhi, xlo, wqhi, wqlo, q_ptr, M, DIMN, DIMN);
    gemm_mma_bf16x3<<<dim3(NKV / 128, M / 128), 256, GEMM_SMEM>>>(
        xhi, xlo, wkhi, wklo, k_ptr, M, NKV, DIMN);
    gemm_mma_bf16x3<<<dim3(NKV / 128, M / 128), 256, GEMM_SMEM>>>(
        xhi, xlo, wvhi, wvlo, v_ptr, M, NKV, DIMN);

    // RMSNorm + RoPE (+gain)
    {
        const int total_warps = M * (HN + KVHN);
        const int blocks = (total_warps * 32 + 255) / 256;
        norm_rope_kernel<<<blocks, 256>>>(qgain);
    }

    // Causal GQA attention + v-orthogonalization
    attn_kernel<<<dim3(TN_ / 8, BN_ * HN), 256>>>();

    // Output projection
    split_kernel<<<(M * DIMN) / 1024, 256>>>(y_ptr, yhi, ylo, M * DIMN);
    gemm_mma_bf16x3<<<dim3(DIMN / 128, M / 128), 256, GEMM_SMEM>>>(
        yhi, ylo, wphi, wplo, out, M, DIMN, DIMN);
}

// round 4
// speedup vs baseline: 1.5105x; 1.0539x over previous
#include <cuda_runtime.h>
#include <cuda_fp16.h>
#include <math.h>

// Problem constants
#define DIMN 2048
#define HN   16
#define KVHN 4
#define HDN  128
#define BN_  4
#define TN_  2048
#define QK_SCALE 0.08838834764831845f   // 128^-0.5
#define EPS_RMS  1e-6f
#define EPS_NORM 1e-12f

// ---------------------------------------------------------------------------
// Scratch (__device__ globals: allocation-free rule)
// ---------------------------------------------------------------------------
__device__ __align__(256) float g_q[(size_t)BN_ * TN_ * DIMN];
__device__ __align__(256) float g_k[(size_t)BN_ * TN_ * KVHN * HDN];
__device__ __align__(256) float g_v[(size_t)BN_ * TN_ * KVHN * HDN];
__device__ __align__(256) float g_y[(size_t)BN_ * TN_ * DIMN];

__device__ __align__(256) __half g_xhi[(size_t)BN_ * TN_ * DIMN];
__device__ __align__(256) __half g_xlo[(size_t)BN_ * TN_ * DIMN];
__device__ __align__(256) __half g_yhi[(size_t)BN_ * TN_ * DIMN];
__device__ __align__(256) __half g_ylo[(size_t)BN_ * TN_ * DIMN];
__device__ __align__(256) __half g_wq[(size_t)DIMN * DIMN];
__device__ __align__(256) __half g_wp[(size_t)DIMN * DIMN];
__device__ __align__(256) __half g_wk[(size_t)KVHN * HDN * DIMN];
__device__ __align__(256) __half g_wv[(size_t)KVHN * HDN * DIMN];

// ---------------------------------------------------------------------------
// Helpers
// ---------------------------------------------------------------------------
__device__ __forceinline__ unsigned smem_u32(const void* p) {
    unsigned a;
    asm("{ .reg .u64 t; cvta.to.shared.u64 t, %1; cvt.u32.u64 %0, t; }"
        : "=r"(a) : "l"(p));
    return a;
}
__device__ __forceinline__ void cp16(unsigned saddr, const void* gaddr) {
    asm volatile("cp.async.cg.shared.global [%0], [%1], 16;"
                 :: "r"(saddr), "l"(gaddr));
}
__device__ __forceinline__ void cp_commit() {
    asm volatile("cp.async.commit_group;" ::: "memory");
}
__device__ __forceinline__ void cp_wait1() {
    asm volatile("cp.async.wait_group 1;" ::: "memory");
}
__device__ __forceinline__ void cp_wait0() {
    asm volatile("cp.async.wait_group 0;" ::: "memory");
}
__device__ __forceinline__ void ldsm_x4(unsigned addr, unsigned* r) {
    asm volatile("ldmatrix.sync.aligned.m8n8.x4.shared.b16 {%0,%1,%2,%3}, [%4];"
                 : "=r"(r[0]), "=r"(r[1]), "=r"(r[2]), "=r"(r[3]) : "r"(addr));
}
__device__ __forceinline__ void mma_f16(float* d, const unsigned* a,
                                        const unsigned* b) {
    asm volatile(
        "mma.sync.aligned.m16n8k16.row.col.f32.f16.f16.f32 "
        "{%0,%1,%2,%3}, {%4,%5,%6,%7}, {%8,%9}, {%0,%1,%2,%3};"
        : "+f"(d[0]), "+f"(d[1]), "+f"(d[2]), "+f"(d[3])
        : "r"(a[0]), "r"(a[1]), "r"(a[2]), "r"(a[3]), "r"(b[0]), "r"(b[1]));
}

// ---------------------------------------------------------------------------
// Split fp32 -> (fp16 hi, fp16 lo)  /  round fp32 -> fp16
// ---------------------------------------------------------------------------
__global__ __launch_bounds__(256) void split2_kernel(
    const float* __restrict__ s, __half* __restrict__ hi,
    __half* __restrict__ lo, int n)
{
    int i = (blockIdx.x * 256 + threadIdx.x) * 4;
    if (i >= n) return;
    float4 v = *(const float4*)(s + i);
    float vv[4] = {v.x, v.y, v.z, v.w};
    __half h[4], l[4];
#pragma unroll
    for (int e = 0; e < 4; e++) {
        h[e] = __float2half(vv[e]);
        l[e] = __float2half(vv[e] - __half2float(h[e]));
    }
    *(uint2*)(hi + i) = *(uint2*)h;
    *(uint2*)(lo + i) = *(uint2*)l;
}

__global__ __launch_bounds__(256) void round16_kernel(
    const float* __restrict__ s, __half* __restrict__ hi, int n)
{
    int i = (blockIdx.x * 256 + threadIdx.x) * 4;
    if (i >= n) return;
    float4 v = *(const float4*)(s + i);
    __half h[4] = {__float2half(v.x), __float2half(v.y),
                   __float2half(v.z), __float2half(v.w)};
    *(uint2*)(hi + i) = *(uint2*)h;
}

// ---------------------------------------------------------------------------
// mma.sync fp16 split-2 GEMM: C[m,n] = sum_k A[m,k]*B[n,k]
// A split into hi+lo fp16, B rounded to fp16. CTA 128x128xBK64, 8 warps (4Mx2N),
// warp tile 32x64. cp.async double buffer, XOR swizzle, ldmatrix.
// Stage = {Ahi, Alo, Bhi} -> 48KB; 2 stages = 96KB; 2 CTAs/SM.
// ---------------------------------------------------------------------------
#define TILE_SZ   16384          // 128 rows x 128 bytes
#define STAGE_SZ  (3 * TILE_SZ)  // Ahi, Alo, Bhi
#define GEMM_SMEM (2 * STAGE_SZ) // 98304

__global__ __launch_bounds__(256, 2) void gemm_mma_f16x2(
    const __half* __restrict__ Ahi, const __half* __restrict__ Alo,
    const __half* __restrict__ Bhi,
    float* __restrict__ C, int M, int N, int K)
{
    extern __shared__ char smem[];
    const unsigned sb = smem_u32(smem);
    const int tid  = threadIdx.x;
    const int wid  = tid >> 5;
    const int lane = tid & 31;
    const int wm   = wid & 3;    // 0..3 -> M offset wm*32
    const int wn   = wid >> 2;   // 0..1 -> N offset wn*64
    const int bm   = blockIdx.y * 128;
    const int bn   = blockIdx.x * 128;

    const __half* tsrc[3] = {Ahi, Alo, Bhi};
    const int tbase[3] = {bm, bm, bn};

    auto stage_load = [&](int c, int buf) {
#pragma unroll
        for (int t = 0; t < 3; t++) {
            const __half* src = tsrc[t];
            const int rb = tbase[t];
#pragma unroll
            for (int part = 0; part < 4; part++) {
                int idx = part * 256 + tid;      // 0..1023
                int r   = idx >> 3;              // 0..127
                int ch  = idx & 7;               // 16B chunk
                const void* g = src + (size_t)(rb + r) * K + c * 64 + ch * 8;
                unsigned so = sb + buf * STAGE_SZ + t * TILE_SZ
                            + r * 128 + ((ch ^ (r & 7)) * 16);
                cp16(so, g);
            }
        }
    };

    float acc[2][8][4];
#pragma unroll
    for (int mi = 0; mi < 2; mi++)
#pragma unroll
        for (int ni = 0; ni < 8; ni++)
#pragma unroll
            for (int e = 0; e < 4; e++) acc[mi][ni][e] = 0.f;

    const int nK = K >> 6;
    stage_load(0, 0);
    cp_commit();

    for (int c = 0; c < nK; c++) {
        const int buf = c & 1;
        if (c + 1 < nK) {
            stage_load(c + 1, buf ^ 1);
            cp_commit();
            cp_wait1();
        } else {
            cp_wait0();
        }
        __syncthreads();

        const unsigned base = sb + buf * STAGE_SZ;
#pragma unroll
        for (int s = 0; s < 4; s++) {
            // A fragments (hi & lo): 2 m16 frags each
            unsigned a_hi[2][4], a_lo[2][4];
#pragma unroll
            for (int mi = 0; mi < 2; mi++) {
                int r  = wm * 32 + mi * 16 + (lane & 15);
                int ch = 2 * s + (lane >> 4);
                unsigned ad = base + r * 128 + ((ch ^ (r & 7)) * 16);
                ldsm_x4(ad, a_hi[mi]);
                ldsm_x4(ad + TILE_SZ, a_lo[mi]);
            }
            // B fragments (hi only): 4 n16 groups -> 8 n8 frags
            unsigned b_hi[4][4];
#pragma unroll
            for (int gi = 0; gi < 4; gi++) {
                int r  = wn * 64 + gi * 16 + (lane & 7) + ((lane >> 4) & 1) * 8;
                int ch = 2 * s + ((lane >> 3) & 1);
                unsigned ad = base + 2 * TILE_SZ + r * 128 + ((ch ^ (r & 7)) * 16);
                ldsm_x4(ad, b_hi[gi]);
            }
            // 16 logical mma x 2 split terms
#pragma unroll
            for (int mi = 0; mi < 2; mi++) {
#pragma unroll
                for (int ni = 0; ni < 8; ni++) {
                    const unsigned bh[2] = {b_hi[ni >> 1][(ni & 1) * 2],
                                            b_hi[ni >> 1][(ni & 1) * 2 + 1]};
                    mma_f16(acc[mi][ni], a_hi[mi], bh);
                    mma_f16(acc[mi][ni], a_lo[mi], bh);
                }
            }
        }
        __syncthreads();
    }

    // Epilogue: direct fp32 stores
#pragma unroll
    for (int mi = 0; mi < 2; mi++) {
#pragma unroll
        for (int ni = 0; ni < 8; ni++) {
            int row = bm + wm * 32 + mi * 16 + (lane >> 2);
            int col = bn + wn * 64 + ni * 8 + (lane & 3) * 2;
            *(float2*)(C + (size_t)row * N + col) =
                make_float2(acc[mi][ni][0], acc[mi][ni][1]);
            *(float2*)(C + (size_t)(row + 8) * N + col) =
                make_float2(acc[mi][ni][2], acc[mi][ni][3]);
        }
    }
}

// ---------------------------------------------------------------------------
// RMSNorm + RoPE (+ q_gain), one warp per (row, head)
// ---------------------------------------------------------------------------
__global__ __launch_bounds__(256) void norm_rope_kernel(const float* __restrict__ qgain)
{
    const int gw   = (blockIdx.x * blockDim.x + threadIdx.x) >> 5;
    const int lane = threadIdx.x & 31;
    const int total = BN_ * TN_ * (HN + KVHN);
    if (gw >= total) return;

    const int head = gw % (HN + KVHN);
    const int row  = gw / (HN + KVHN);
    const int t    = row % TN_;

    float* ptr;
    float gain = 1.f;
    if (head < HN) {
        ptr = g_q + (size_t)row * DIMN + head * HDN;
        gain = qgain[head];
    } else {
        ptr = g_k + (size_t)row * (KVHN * HDN) + (head - HN) * HDN;
    }

    float4 v = *(const float4*)(ptr + lane * 4);
    float ss = v.x * v.x + v.y * v.y + v.z * v.z + v.w * v.w;
#pragma unroll
    for (int o = 16; o; o >>= 1) ss += __shfl_xor_sync(0xffffffffu, ss, o);
    const float r = rsqrtf(ss * (1.f / 128.f) + EPS_RMS);
    v.x *= r; v.y *= r; v.z *= r; v.w *= r;

    float4 p;
    p.x = __shfl_xor_sync(0xffffffffu, v.x, 8);
    p.y = __shfl_xor_sync(0xffffffffu, v.y, 8);
    p.z = __shfl_xor_sync(0xffffffffu, v.z, 8);
    p.w = __shfl_xor_sync(0xffffffffu, v.w, 8);

    if (lane < 16) {
        const int base = (lane & 7) * 4;
        float* ve = &v.x;
        const float* pe = &p.x;
#pragma unroll
        for (int e = 0; e < 4; e++) {
            const int j = base + e;
            const float inv = powf(10000.f, -(float)j / 32.f);
            float s, c;
            sincosf((float)t * inv, &s, &c);
            if (lane < 8) ve[e] = ve[e] * c - pe[e] * s;
            else          ve[e] = ve[e] * c + pe[e] * s;
        }
    }
    v.x *= gain; v.y *= gain; v.z *= gain; v.w *= gain;
    *(float4*)(ptr + lane * 4) = v;
}

// ---------------------------------------------------------------------------
// Causal GQA flash attention + v-orthogonalization (fp32)
// ---------------------------------------------------------------------------
__global__ __launch_bounds__(256) void attn_kernel()
{
    __shared__ float ks[32][132];
    __shared__ float vs[32][132];
    __shared__ float qs[8][132];

    const int bh   = blockIdx.y;
    const int b    = bh / HN;
    const int h    = bh % HN;
    const int kvh  = h / (HN / KVHN);
    const int t0   = blockIdx.x * 8;
    const int warp = threadIdx.x >> 5;
    const int lane = threadIdx.x & 31;
    const int t    = t0 + warp;

    {
        const float* qp = g_q + ((size_t)(b * TN_ + t)) * DIMN + h * HDN;
        *(float4*)&qs[warp][lane * 4] = *(const float4*)(qp + lane * 4);
    }

    float a0 = 0.f, a1 = 0.f, a2 = 0.f, a3 = 0.f;
    float m = -INFINITY, l = 0.f;

    const int t_max = t0 + 7;
    const int nkb = (t_max >> 5) + 1;

    for (int kb = 0; kb < nkb; kb++) {
        const int j0 = kb * 32;
        __syncthreads();
#pragma unroll
        for (int r = 0; r < 4; r++) {
            const int idx = r * 256 + threadIdx.x;
            const int key = idx >> 5;
            const int c4  = idx & 31;
            const size_t gbase = ((size_t)(b * TN_ + j0 + key)) * (KVHN * HDN) + kvh * HDN + c4 * 4;
            *(float4*)&ks[key][c4 * 4] = *(const float4*)(g_k + gbase);
            *(float4*)&vs[key][c4 * 4] = *(const float4*)(g_v + gbase);
        }
        __syncthreads();

        if (j0 > t) continue;

        const int j = j0 + lane;
        float s;
        if (j <= t) {
            s = 0.f;
#pragma unroll
            for (int c4 = 0; c4 < 32; c4++) {
                float4 kk = *(const float4*)&ks[lane][c4 * 4];
                float4 qq = *(const float4*)&qs[warp][c4 * 4];
                s += qq.x * kk.x + qq.y * kk.y + qq.z * kk.z + qq.w * kk.w;
            }
            s *= QK_SCALE;
        } else {
            s = -INFINITY;
        }

        float smax = s;
#pragma unroll
        for (int o = 16; o; o >>= 1)
            smax = fmaxf(smax, __shfl_xor_sync(0xffffffffu, smax, o));
        const float mnew = fmaxf(m, smax);
        const float corr = __expf(m - mnew);
        float pp = (j <= t) ? __expf(s - mnew) : 0.f;
        float psum = pp;
#pragma unroll
        for (int o = 16; o; o >>= 1) psum += __shfl_xor_sync(0xffffffffu, psum, o);
        l = l * corr + psum;
        a0 *= corr; a1 *= corr; a2 *= corr; a3 *= corr;
        m = mnew;

#pragma unroll
        for (int jj = 0; jj < 32; jj++) {
            const float pj = __shfl_sync(0xffffffffu, pp, jj);
            float4 vv = *(const float4*)&vs[jj][lane * 4];
            a0 += pj * vv.x; a1 += pj * vv.y; a2 += pj * vv.z; a3 += pj * vv.w;
        }
    }

    const float inv_l = 1.f / l;
    a0 *= inv_l; a1 *= inv_l; a2 *= inv_l; a3 *= inv_l;

    const float* vp = g_v + ((size_t)(b * TN_ + t)) * (KVHN * HDN) + kvh * HDN;
    float4 vt = *(const float4*)(vp + lane * 4);
    float nn = vt.x * vt.x + vt.y * vt.y + vt.z * vt.z + vt.w * vt.w;
#pragma unroll
    for (int o = 16; o; o >>= 1) nn += __shfl_xor_sync(0xffffffffu, nn, o);
    const float invn = 1.f / fmaxf(sqrtf(nn), EPS_NORM);
    float dotv = a0 * vt.x + a1 * vt.y + a2 * vt.z + a3 * vt.w;
#pragma unroll
    for (int o = 16; o; o >>= 1) dotv += __shfl_xor_sync(0xffffffffu, dotv, o);
    const float cfac = dotv * invn * invn;
    a0 -= cfac * vt.x; a1 -= cfac * vt.y; a2 -= cfac * vt.z; a3 -= cfac * vt.w;

    float* yp = g_y + ((size_t)(b * TN_ + t)) * DIMN + h * HDN;
    *(float4*)(yp + lane * 4) = make_float4(a0, a1, a2, a3);
}

// ---------------------------------------------------------------------------
// Launch
// ---------------------------------------------------------------------------
extern "C" void kernel_launch(void* const* d_in, const int* in_sizes, int n_in,
                              void* d_out, int out_size)
{
    const float* x     = (const float*)d_in[0];
    const float* Wq    = (const float*)d_in[1];
    const float* Wk    = (const float*)d_in[2];
    const float* Wv    = (const float*)d_in[3];
    const float* Wproj = (const float*)d_in[4];
    const float* qgain = (const float*)d_in[5];
    float* out = (float*)d_out;

    float *q_ptr, *k_ptr, *v_ptr, *y_ptr;
    cudaGetSymbolAddress((void**)&q_ptr, g_q);
    cudaGetSymbolAddress((void**)&k_ptr, g_k);
    cudaGetSymbolAddress((void**)&v_ptr, g_v);
    cudaGetSymbolAddress((void**)&y_ptr, g_y);
    __half *xhi, *xlo, *yhi, *ylo, *wq, *wk, *wv, *wp;
    cudaGetSymbolAddress((void**)&xhi, g_xhi); cudaGetSymbolAddress((void**)&xlo, g_xlo);
    cudaGetSymbolAddress((void**)&yhi, g_yhi); cudaGetSymbolAddress((void**)&ylo, g_ylo);
    cudaGetSymbolAddress((void**)&wq, g_wq);   cudaGetSymbolAddress((void**)&wk, g_wk);
    cudaGetSymbolAddress((void**)&wv, g_wv);   cudaGetSymbolAddress((void**)&wp, g_wp);

    cudaFuncSetAttribute(gemm_mma_f16x2, cudaFuncAttributeMaxDynamicSharedMemorySize, GEMM_SMEM);

    const int M = BN_ * TN_;            // 8192
    const int NKV = KVHN * HDN;         // 512

    // Prepare fp16 operands
    split2_kernel<<<(M * DIMN) / 1024, 256>>>(x, xhi, xlo, M * DIMN);
    round16_kernel<<<(DIMN * DIMN) / 1024, 256>>>(Wq, wq, DIMN * DIMN);
    round16_kernel<<<(NKV * DIMN) / 1024, 256>>>(Wk, wk, NKV * DIMN);
    round16_kernel<<<(NKV * DIMN) / 1024, 256>>>(Wv, wv, NKV * DIMN);
    round16_kernel<<<(DIMN * DIMN) / 1024, 256>>>(Wproj, wp, DIMN * DIMN);

    // QKV projections (mma.sync fp16 split-2)
    gemm_mma_f16x2<<<dim3(DIMN / 128, M / 128), 256, GEMM_SMEM>>>(
        xhi, xlo, wq, q_ptr, M, DIMN, DIMN);
    gemm_mma_f16x2<<<dim3(NKV / 128, M / 128), 256, GEMM_SMEM>>>(
        xhi, xlo, wk, k_ptr, M, NKV, DIMN);
    gemm_mma_f16x2<<<dim3(NKV / 128, M / 128), 256, GEMM_SMEM>>>(
        xhi, xlo, wv, v_ptr, M, NKV, DIMN);

    // RMSNorm + RoPE (+gain)
    {
        const int total_warps = M * (HN + KVHN);
        const int blocks = (total_warps * 32 + 255) / 256;
        norm_rope_kernel<<<blocks, 256>>>(qgain);
    }

    // Causal GQA attention + v-orthogonalization
    attn_kernel<<<dim3(TN_ / 8, BN_ * HN), 256>>>();

    // Output projection
    split2_kernel<<<(M * DIMN) / 1024, 256>>>(y_ptr, yhi, ylo, M * DIMN);
    gemm_mma_f16x2<<<dim3(DIMN / 128, M / 128), 256, GEMM_SMEM>>>(
        yhi, ylo, wp, out, M, DIMN, DIMN);
}

// round 5
// speedup vs baseline: 1.5838x; 1.0485x over previous
#include <cuda_runtime.h>
#include <cuda_fp16.h>
#include <math.h>

// Problem constants
#define DIMN 2048
#define HN   16
#define KVHN 4
#define HDN  128
#define BN_  4
#define TN_  2048
#define QK_SCALE 0.08838834764831845f   // 128^-0.5
#define EPS_RMS  1e-6f
#define EPS_NORM 1e-12f

// ---------------------------------------------------------------------------
// Scratch (__device__ globals: allocation-free rule)
// ---------------------------------------------------------------------------
__device__ __align__(256) float g_q[(size_t)BN_ * TN_ * DIMN];
__device__ __align__(256) float g_k[(size_t)BN_ * TN_ * KVHN * HDN];
__device__ __align__(256) float g_v[(size_t)BN_ * TN_ * KVHN * HDN];
__device__ __align__(256) float g_y[(size_t)BN_ * TN_ * DIMN];

__device__ __align__(256) __half g_xhi[(size_t)BN_ * TN_ * DIMN];
__device__ __align__(256) __half g_xlo[(size_t)BN_ * TN_ * DIMN];
__device__ __align__(256) __half g_yhi[(size_t)BN_ * TN_ * DIMN];
__device__ __align__(256) __half g_ylo[(size_t)BN_ * TN_ * DIMN];
__device__ __align__(256) __half g_wq[(size_t)DIMN * DIMN];
__device__ __align__(256) __half g_wp[(size_t)DIMN * DIMN];
__device__ __align__(256) __half g_wk[(size_t)KVHN * HDN * DIMN];
__device__ __align__(256) __half g_wv[(size_t)KVHN * HDN * DIMN];

// ---------------------------------------------------------------------------
// Helpers
// ---------------------------------------------------------------------------
__device__ __forceinline__ unsigned smem_u32(const void* p) {
    unsigned a;
    asm("{ .reg .u64 t; cvta.to.shared.u64 t, %1; cvt.u32.u64 %0, t; }"
        : "=r"(a) : "l"(p));
    return a;
}
__device__ __forceinline__ void cp16(unsigned saddr, const void* gaddr) {
    asm volatile("cp.async.cg.shared.global [%0], [%1], 16;"
                 :: "r"(saddr), "l"(gaddr));
}
__device__ __forceinline__ void cp_commit() {
    asm volatile("cp.async.commit_group;" ::: "memory");
}
__device__ __forceinline__ void cp_wait1() {
    asm volatile("cp.async.wait_group 1;" ::: "memory");
}
__device__ __forceinline__ void cp_wait0() {
    asm volatile("cp.async.wait_group 0;" ::: "memory");
}
__device__ __forceinline__ void ldsm_x4(unsigned addr, unsigned* r) {
    asm volatile("ldmatrix.sync.aligned.m8n8.x4.shared.b16 {%0,%1,%2,%3}, [%4];"
                 : "=r"(r[0]), "=r"(r[1]), "=r"(r[2]), "=r"(r[3]) : "r"(addr));
}
__device__ __forceinline__ void mma_f16(float* d, const unsigned* a,
                                        const unsigned* b) {
    asm volatile(
        "mma.sync.aligned.m16n8k16.row.col.f32.f16.f16.f32 "
        "{%0,%1,%2,%3}, {%4,%5,%6,%7}, {%8,%9}, {%0,%1,%2,%3};"
        : "+f"(d[0]), "+f"(d[1]), "+f"(d[2]), "+f"(d[3])
        : "r"(a[0]), "r"(a[1]), "r"(a[2]), "r"(a[3]), "r"(b[0]), "r"(b[1]));
}

// ---------------------------------------------------------------------------
// Prep: split fp32 -> (fp16 hi, lo); round all 4 weight matrices in one launch
// ---------------------------------------------------------------------------
__global__ __launch_bounds__(256) void split2_kernel(
    const float* __restrict__ s, __half* __restrict__ hi,
    __half* __restrict__ lo, int n)
{
    int i = (blockIdx.x * 256 + threadIdx.x) * 4;
    if (i >= n) return;
    float4 v = *(const float4*)(s + i);
    float vv[4] = {v.x, v.y, v.z, v.w};
    __half h[4], l[4];
#pragma unroll
    for (int e = 0; e < 4; e++) {
        h[e] = __float2half(vv[e]);
        l[e] = __float2half(vv[e] - __half2float(h[e]));
    }
    *(uint2*)(hi + i) = *(uint2*)h;
    *(uint2*)(lo + i) = *(uint2*)l;
}

// sizes in float4 units: Wq 1048576, Wk 262144, Wv 262144, Wp 1048576
__global__ __launch_bounds__(256) void round_all_kernel(
    const float* __restrict__ Wq, const float* __restrict__ Wk,
    const float* __restrict__ Wv, const float* __restrict__ Wp,
    __half* __restrict__ wq, __half* __restrict__ wk,
    __half* __restrict__ wv, __half* __restrict__ wp)
{
    int i = blockIdx.x * 256 + threadIdx.x;     // float4 index, < 2621440
    const float* s; __half* d; int off;
    if (i < 1048576)      { s = Wq; d = wq; off = i; }
    else if (i < 1310720) { s = Wk; d = wk; off = i - 1048576; }
    else if (i < 1572864) { s = Wv; d = wv; off = i - 1310720; }
    else                  { s = Wp; d = wp; off = i - 1572864; }
    float4 v = *(const float4*)(s + off * 4);
    __half h[4] = {__float2half(v.x), __float2half(v.y),
                   __float2half(v.z), __float2half(v.w)};
    *(uint2*)(d + off * 4) = *(uint2*)h;
}

// ---------------------------------------------------------------------------
// mma.sync fp16 split-2 GEMM: C[m,n] = sum_k A[m,k]*B[n,k]
// A split hi+lo fp16, B fp16. CTA 128x128xBK64, 512 threads, 16 warps (4Mx4N),
// warp tile 32x32 -> acc 32 regs/thread, no spills. cp.async double buffer.
// ---------------------------------------------------------------------------
#define TILE_SZ   16384          // 128 rows x 128 bytes
#define STAGE_SZ  (3 * TILE_SZ)  // Ahi, Alo, B
#define GEMM_SMEM (2 * STAGE_SZ) // 98304

__global__ __launch_bounds__(512) void gemm_mma_f16x2(
    const __half* __restrict__ Ahi, const __half* __restrict__ Alo,
    const __half* __restrict__ Bh,
    float* __restrict__ C, int M, int N, int K)
{
    extern __shared__ char smem[];
    const unsigned sb = smem_u32(smem);
    const int tid  = threadIdx.x;
    const int wid  = tid >> 5;
    const int lane = tid & 31;
    const int wm   = wid & 3;    // M offset wm*32
    const int wn   = wid >> 2;   // N offset wn*32
    const int bm   = blockIdx.y * 128;
    const int bn   = blockIdx.x * 128;

    const __half* tsrc[3] = {Ahi, Alo, Bh};
    const int tbase[3] = {bm, bm, bn};

    auto stage_load = [&](int c, int buf) {
#pragma unroll
        for (int t = 0; t < 3; t++) {
            const __half* src = tsrc[t];
            const int rb = tbase[t];
#pragma unroll
            for (int part = 0; part < 2; part++) {
                int idx = part * 512 + tid;      // 0..1023
                int r   = idx >> 3;              // 0..127
                int ch  = idx & 7;               // 16B chunk
                const void* g = src + (size_t)(rb + r) * K + c * 64 + ch * 8;
                unsigned so = sb + buf * STAGE_SZ + t * TILE_SZ
                            + r * 128 + ((ch ^ (r & 7)) * 16);
                cp16(so, g);
            }
        }
    };

    float acc[2][4][4];
#pragma unroll
    for (int mi = 0; mi < 2; mi++)
#pragma unroll
        for (int ni = 0; ni < 4; ni++)
#pragma unroll
            for (int e = 0; e < 4; e++) acc[mi][ni][e] = 0.f;

    const int nK = K >> 6;
    stage_load(0, 0);
    cp_commit();

    for (int c = 0; c < nK; c++) {
        const int buf = c & 1;
        if (c + 1 < nK) {
            stage_load(c + 1, buf ^ 1);
            cp_commit();
            cp_wait1();
        } else {
            cp_wait0();
        }
        __syncthreads();

        const unsigned base = sb + buf * STAGE_SZ;
#pragma unroll
        for (int s = 0; s < 4; s++) {
            unsigned a_hi[2][4], a_lo[2][4];
#pragma unroll
            for (int mi = 0; mi < 2; mi++) {
                int r  = wm * 32 + mi * 16 + (lane & 15);
                int ch = 2 * s + (lane >> 4);
                unsigned ad = base + r * 128 + ((ch ^ (r & 7)) * 16);
                ldsm_x4(ad, a_hi[mi]);
                ldsm_x4(ad + TILE_SZ, a_lo[mi]);
            }
            unsigned b_h[2][4];
#pragma unroll
            for (int gi = 0; gi < 2; gi++) {
                int r  = wn * 32 + gi * 16 + (lane & 7) + ((lane >> 4) & 1) * 8;
                int ch = 2 * s + ((lane >> 3) & 1);
                unsigned ad = base + 2 * TILE_SZ + r * 128 + ((ch ^ (r & 7)) * 16);
                ldsm_x4(ad, b_h[gi]);
            }
#pragma unroll
            for (int mi = 0; mi < 2; mi++) {
#pragma unroll
                for (int ni = 0; ni < 4; ni++) {
                    const unsigned bh[2] = {b_h[ni >> 1][(ni & 1) * 2],
                                            b_h[ni >> 1][(ni & 1) * 2 + 1]};
                    mma_f16(acc[mi][ni], a_hi[mi], bh);
                    mma_f16(acc[mi][ni], a_lo[mi], bh);
                }
            }
        }
        __syncthreads();
    }

#pragma unroll
    for (int mi = 0; mi < 2; mi++) {
#pragma unroll
        for (int ni = 0; ni < 4; ni++) {
            int row = bm + wm * 32 + mi * 16 + (lane >> 2);
            int col = bn + wn * 32 + ni * 8 + (lane & 3) * 2;
            *(float2*)(C + (size_t)row * N + col) =
                make_float2(acc[mi][ni][0], acc[mi][ni][1]);
            *(float2*)(C + (size_t)(row + 8) * N + col) =
                make_float2(acc[mi][ni][2], acc[mi][ni][3]);
        }
    }
}

// ---------------------------------------------------------------------------
// RMSNorm + RoPE (+ q_gain), one warp per (row, head)
// ---------------------------------------------------------------------------
__global__ __launch_bounds__(256) void norm_rope_kernel(const float* __restrict__ qgain)
{
    const int gw   = (blockIdx.x * blockDim.x + threadIdx.x) >> 5;
    const int lane = threadIdx.x & 31;
    const int total = BN_ * TN_ * (HN + KVHN);
    if (gw >= total) return;

    const int head = gw % (HN + KVHN);
    const int row  = gw / (HN + KVHN);
    const int t    = row % TN_;

    float* ptr;
    float gain = 1.f;
    if (head < HN) {
        ptr = g_q + (size_t)row * DIMN + head * HDN;
        gain = qgain[head];
    } else {
        ptr = g_k + (size_t)row * (KVHN * HDN) + (head - HN) * HDN;
    }

    float4 v = *(const float4*)(ptr + lane * 4);
    float ss = v.x * v.x + v.y * v.y + v.z * v.z + v.w * v.w;
#pragma unroll
    for (int o = 16; o; o >>= 1) ss += __shfl_xor_sync(0xffffffffu, ss, o);
    const float r = rsqrtf(ss * (1.f / 128.f) + EPS_RMS);
    v.x *= r; v.y *= r; v.z *= r; v.w *= r;

    float4 p;
    p.x = __shfl_xor_sync(0xffffffffu, v.x, 8);
    p.y = __shfl_xor_sync(0xffffffffu, v.y, 8);
    p.z = __shfl_xor_sync(0xffffffffu, v.z, 8);
    p.w = __shfl_xor_sync(0xffffffffu, v.w, 8);

    if (lane < 16) {
        const int base = (lane & 7) * 4;
        float* ve = &v.x;
        const float* pe = &p.x;
#pragma unroll
        for (int e = 0; e < 4; e++) {
            const int j = base + e;
            const float inv = powf(10000.f, -(float)j / 32.f);
            float s, c;
            sincosf((float)t * inv, &s, &c);
            if (lane < 8) ve[e] = ve[e] * c - pe[e] * s;
            else          ve[e] = ve[e] * c + pe[e] * s;
        }
    }
    v.x *= gain; v.y *= gain; v.z *= gain; v.w *= gain;
    *(float4*)(ptr + lane * 4) = v;
}

// ---------------------------------------------------------------------------
// Causal GQA flash attention + v-orthogonalization (fp32).
// 512 threads, 16 warps, each warp owns one query row; 16 rows share K/V tiles.
// ---------------------------------------------------------------------------
__global__ __launch_bounds__(512) void attn_kernel()
{
    __shared__ float ks[32][132];
    __shared__ float vs[32][132];
    __shared__ float qs[16][132];

    const int bh   = blockIdx.y;
    const int b    = bh / HN;
    const int h    = bh % HN;
    const int kvh  = h / (HN / KVHN);
    const int t0   = blockIdx.x * 16;
    const int warp = threadIdx.x >> 5;
    const int lane = threadIdx.x & 31;
    const int t    = t0 + warp;

    {
        const float* qp = g_q + ((size_t)(b * TN_ + t)) * DIMN + h * HDN;
        *(float4*)&qs[warp][lane * 4] = *(const float4*)(qp + lane * 4);
    }

    float a0 = 0.f, a1 = 0.f, a2 = 0.f, a3 = 0.f;
    float m = -INFINITY, l = 0.f;

    const int t_max = t0 + 15;
    const int nkb = (t_max >> 5) + 1;

    for (int kb = 0; kb < nkb; kb++) {
        const int j0 = kb * 32;
        __syncthreads();
#pragma unroll
        for (int r = 0; r < 2; r++) {
            const int idx = r * 512 + threadIdx.x;  // 0..1023
            const int key = idx >> 5;
            const int c4  = idx & 31;
            const size_t gbase = ((size_t)(b * TN_ + j0 + key)) * (KVHN * HDN) + kvh * HDN + c4 * 4;
            *(float4*)&ks[key][c4 * 4] = *(const float4*)(g_k + gbase);
            *(float4*)&vs[key][c4 * 4] = *(const float4*)(g_v + gbase);
        }
        __syncthreads();

        if (j0 > t) continue;

        const int j = j0 + lane;
        float s;
        if (j <= t) {
            s = 0.f;
#pragma unroll
            for (int c4 = 0; c4 < 32; c4++) {
                float4 kk = *(const float4*)&ks[lane][c4 * 4];
                float4 qq = *(const float4*)&qs[warp][c4 * 4];
                s += qq.x * kk.x + qq.y * kk.y + qq.z * kk.z + qq.w * kk.w;
            }
            s *= QK_SCALE;
        } else {
            s = -INFINITY;
        }

        float smax = s;
#pragma unroll
        for (int o = 16; o; o >>= 1)
            smax = fmaxf(smax, __shfl_xor_sync(0xffffffffu, smax, o));
        const float mnew = fmaxf(m, smax);
        const float corr = __expf(m - mnew);
        float pp = (j <= t) ? __expf(s - mnew) : 0.f;
        float psum = pp;
#pragma unroll
        for (int o = 16; o; o >>= 1) psum += __shfl_xor_sync(0xffffffffu, psum, o);
        l = l * corr + psum;
        a0 *= corr; a1 *= corr; a2 *= corr; a3 *= corr;
        m = mnew;

#pragma unroll
        for (int jj = 0; jj < 32; jj++) {
            const float pj = __shfl_sync(0xffffffffu, pp, jj);
            float4 vv = *(const float4*)&vs[jj][lane * 4];
            a0 += pj * vv.x; a1 += pj * vv.y; a2 += pj * vv.z; a3 += pj * vv.w;
        }
    }

    const float inv_l = 1.f / l;
    a0 *= inv_l; a1 *= inv_l; a2 *= inv_l; a3 *= inv_l;

    const float* vp = g_v + ((size_t)(b * TN_ + t)) * (KVHN * HDN) + kvh * HDN;
    float4 vt = *(const float4*)(vp + lane * 4);
    float nn = vt.x * vt.x + vt.y * vt.y + vt.z * vt.z + vt.w * vt.w;
#pragma unroll
    for (int o = 16; o; o >>= 1) nn += __shfl_xor_sync(0xffffffffu, nn, o);
    const float invn = 1.f / fmaxf(sqrtf(nn), EPS_NORM);
    float dotv = a0 * vt.x + a1 * vt.y + a2 * vt.z + a3 * vt.w;
#pragma unroll
    for (int o = 16; o; o >>= 1) dotv += __shfl_xor_sync(0xffffffffu, dotv, o);
    const float cfac = dotv * invn * invn;
    a0 -= cfac * vt.x; a1 -= cfac * vt.y; a2 -= cfac * vt.z; a3 -= cfac * vt.w;

    float* yp = g_y + ((size_t)(b * TN_ + t)) * DIMN + h * HDN;
    *(float4*)(yp + lane * 4) = make_float4(a0, a1, a2, a3);
}

// ---------------------------------------------------------------------------
// Launch
// ---------------------------------------------------------------------------
extern "C" void kernel_launch(void* const* d_in, const int* in_sizes, int n_in,
                              void* d_out, int out_size)
{
    const float* x     = (const float*)d_in[0];
    const float* Wq    = (const float*)d_in[1];
    const float* Wk    = (const float*)d_in[2];
    const float* Wv    = (const float*)d_in[3];
    const float* Wproj = (const float*)d_in[4];
    const float* qgain = (const float*)d_in[5];
    float* out = (float*)d_out;

    float *q_ptr, *k_ptr, *v_ptr, *y_ptr;
    cudaGetSymbolAddress((void**)&q_ptr, g_q);
    cudaGetSymbolAddress((void**)&k_ptr, g_k);
    cudaGetSymbolAddress((void**)&v_ptr, g_v);
    cudaGetSymbolAddress((void**)&y_ptr, g_y);
    __half *xhi, *xlo, *yhi, *ylo, *wq, *wk, *wv, *wp;
    cudaGetSymbolAddress((void**)&xhi, g_xhi); cudaGetSymbolAddress((void**)&xlo, g_xlo);
    cudaGetSymbolAddress((void**)&yhi, g_yhi); cudaGetSymbolAddress((void**)&ylo, g_ylo);
    cudaGetSymbolAddress((void**)&wq, g_wq);   cudaGetSymbolAddress((void**)&wk, g_wk);
    cudaGetSymbolAddress((void**)&wv, g_wv);   cudaGetSymbolAddress((void**)&wp, g_wp);

    cudaFuncSetAttribute(gemm_mma_f16x2, cudaFuncAttributeMaxDynamicSharedMemorySize, GEMM_SMEM);

    const int M = BN_ * TN_;            // 8192
    const int NKV = KVHN * HDN;         // 512

    // Prep (2 launches so the ncu capture window lands on GEMMs)
    split2_kernel<<<(M * DIMN) / 1024, 256>>>(x, xhi, xlo, M * DIMN);
    round_all_kernel<<<10240, 256>>>(Wq, Wk, Wv, Wproj, wq, wk, wv, wp);

    // QKV projections (mma.sync fp16 split-2)
    gemm_mma_f16x2<<<dim3(DIMN / 128, M / 128), 512, GEMM_SMEM>>>(
        xhi, xlo, wq, q_ptr, M, DIMN, DIMN);
    gemm_mma_f16x2<<<dim3(NKV / 128, M / 128), 512, GEMM_SMEM>>>(
        xhi, xlo, wk, k_ptr, M, NKV, DIMN);
    gemm_mma_f16x2<<<dim3(NKV / 128, M / 128), 512, GEMM_SMEM>>>(
        xhi, xlo, wv, v_ptr, M, NKV, DIMN);

    // RMSNorm + RoPE (+gain)
    {
        const int total_warps = M * (HN + KVHN);
        const int blocks = (total_warps * 32 + 255) / 256;
        norm_rope_kernel<<<blocks, 256>>>(qgain);
    }

    // Causal GQA attention + v-orthogonalization
    attn_kernel<<<dim3(TN_ / 16, BN_ * HN), 512>>>();

    // Output projection
    split2_kernel<<<(M * DIMN) / 1024, 256>>>(y_ptr, yhi, ylo, M * DIMN);
    gemm_mma_f16x2<<<dim3(DIMN / 128, M / 128), 512, GEMM_SMEM>>>(
        yhi, ylo, wp, out, M, DIMN, DIMN);
}

// round 6
// speedup vs baseline: 6.6362x; 4.1901x over previous
#include <cuda_runtime.h>
#include <cuda_fp16.h>
#include <math.h>

// Problem constants
#define DIMN 2048
#define HN   16
#define KVHN 4
#define HDN  128
#define BN_  4
#define TN_  2048
#define QK_SCALE 0.08838834764831845f   // 128^-0.5
#define EPS_RMS  1e-6f
#define EPS_NORM 1e-12f

// ---------------------------------------------------------------------------
// Scratch (__device__ globals: allocation-free rule)
// ---------------------------------------------------------------------------
__device__ __align__(256) float g_q[(size_t)BN_ * TN_ * DIMN];
__device__ __align__(256) float g_k[(size_t)BN_ * TN_ * KVHN * HDN];
__device__ __align__(256) float g_v[(size_t)BN_ * TN_ * KVHN * HDN];
__device__ __align__(256) float g_y[(size_t)BN_ * TN_ * DIMN];

__device__ __align__(256) __half g_xhi[(size_t)BN_ * TN_ * DIMN];
__device__ __align__(256) __half g_xlo[(size_t)BN_ * TN_ * DIMN];
__device__ __align__(256) __half g_yhi[(size_t)BN_ * TN_ * DIMN];
__device__ __align__(256) __half g_ylo[(size_t)BN_ * TN_ * DIMN];
__device__ __align__(256) __half g_wq[(size_t)DIMN * DIMN];
__device__ __align__(256) __half g_wp[(size_t)DIMN * DIMN];
__device__ __align__(256) __half g_wk[(size_t)KVHN * HDN * DIMN];
__device__ __align__(256) __half g_wv[(size_t)KVHN * HDN * DIMN];

// fp16 operands for tensor-core attention
__device__ __align__(256) __half g_qh[(size_t)BN_ * TN_ * DIMN];
__device__ __align__(256) __half g_ql[(size_t)BN_ * TN_ * DIMN];
__device__ __align__(256) __half g_kh[(size_t)BN_ * TN_ * KVHN * HDN];
__device__ __align__(256) __half g_kl[(size_t)BN_ * TN_ * KVHN * HDN];
__device__ __align__(256) __half g_vh[(size_t)BN_ * TN_ * KVHN * HDN];
__device__ __align__(256) __half g_vl[(size_t)BN_ * TN_ * KVHN * HDN];

// ---------------------------------------------------------------------------
// Helpers
// ---------------------------------------------------------------------------
__device__ __forceinline__ unsigned smem_u32(const void* p) {
    unsigned a;
    asm("{ .reg .u64 t; cvta.to.shared.u64 t, %1; cvt.u32.u64 %0, t; }"
        : "=r"(a) : "l"(p));
    return a;
}
__device__ __forceinline__ void cp16(unsigned saddr, const void* gaddr) {
    asm volatile("cp.async.cg.shared.global [%0], [%1], 16;"
                 :: "r"(saddr), "l"(gaddr));
}
__device__ __forceinline__ void cp_commit() {
    asm volatile("cp.async.commit_group;" ::: "memory");
}
__device__ __forceinline__ void cp_wait1() {
    asm volatile("cp.async.wait_group 1;" ::: "memory");
}
__device__ __forceinline__ void cp_wait0() {
    asm volatile("cp.async.wait_group 0;" ::: "memory");
}
__device__ __forceinline__ void ldsm_x4(unsigned addr, unsigned* r) {
    asm volatile("ldmatrix.sync.aligned.m8n8.x4.shared.b16 {%0,%1,%2,%3}, [%4];"
                 : "=r"(r[0]), "=r"(r[1]), "=r"(r[2]), "=r"(r[3]) : "r"(addr));
}
__device__ __forceinline__ void ldsm_x4_t(unsigned addr, unsigned* r) {
    asm volatile("ldmatrix.sync.aligned.m8n8.x4.trans.shared.b16 {%0,%1,%2,%3}, [%4];"
                 : "=r"(r[0]), "=r"(r[1]), "=r"(r[2]), "=r"(r[3]) : "r"(addr));
}
__device__ __forceinline__ void mma_f16(float* d, const unsigned* a,
                                        const unsigned* b) {
    asm volatile(
        "mma.sync.aligned.m16n8k16.row.col.f32.f16.f16.f32 "
        "{%0,%1,%2,%3}, {%4,%5,%6,%7}, {%8,%9}, {%0,%1,%2,%3};"
        : "+f"(d[0]), "+f"(d[1]), "+f"(d[2]), "+f"(d[3])
        : "r"(a[0]), "r"(a[1]), "r"(a[2]), "r"(a[3]), "r"(b[0]), "r"(b[1]));
}
__device__ __forceinline__ unsigned packh(__half a, __half b) {
    __half2 t = __halves2half2(a, b);
    return *(unsigned*)&t;
}

// ---------------------------------------------------------------------------
// Prep kernels
// ---------------------------------------------------------------------------
__global__ __launch_bounds__(256) void split2_kernel(
    const float* __restrict__ s, __half* __restrict__ hi,
    __half* __restrict__ lo, int n)
{
    int i = (blockIdx.x * 256 + threadIdx.x) * 4;
    if (i >= n) return;
    float4 v = *(const float4*)(s + i);
    float vv[4] = {v.x, v.y, v.z, v.w};
    __half h[4], l[4];
#pragma unroll
    for (int e = 0; e < 4; e++) {
        h[e] = __float2half_rn(vv[e]);
        l[e] = __float2half_rn(vv[e] - __half2float(h[e]));
    }
    *(uint2*)(hi + i) = *(uint2*)h;
    *(uint2*)(lo + i) = *(uint2*)l;
}

__global__ __launch_bounds__(256) void round_all_kernel(
    const float* __restrict__ Wq, const float* __restrict__ Wk,
    const float* __restrict__ Wv, const float* __restrict__ Wp,
    __half* __restrict__ wq, __half* __restrict__ wk,
    __half* __restrict__ wv, __half* __restrict__ wp)
{
    int i = blockIdx.x * 256 + threadIdx.x;     // float4 index
    const float* s; __half* d; int off;
    if (i < 1048576)      { s = Wq; d = wq; off = i; }
    else if (i < 1310720) { s = Wk; d = wk; off = i - 1048576; }
    else if (i < 1572864) { s = Wv; d = wv; off = i - 1310720; }
    else                  { s = Wp; d = wp; off = i - 1572864; }
    float4 v = *(const float4*)(s + off * 4);
    __half h[4] = {__float2half(v.x), __float2half(v.y),
                   __float2half(v.z), __float2half(v.w)};
    *(uint2*)(d + off * 4) = *(uint2*)h;
}

// ---------------------------------------------------------------------------
// mma.sync fp16 split-2 GEMM (unchanged from R5)
// ---------------------------------------------------------------------------
#define TILE_SZ   16384
#define STAGE_SZ  (3 * TILE_SZ)
#define GEMM_SMEM (2 * STAGE_SZ)

__global__ __launch_bounds__(512) void gemm_mma_f16x2(
    const __half* __restrict__ Ahi, const __half* __restrict__ Alo,
    const __half* __restrict__ Bh,
    float* __restrict__ C, int M, int N, int K)
{
    extern __shared__ char smem[];
    const unsigned sb = smem_u32(smem);
    const int tid  = threadIdx.x;
    const int wid  = tid >> 5;
    const int lane = tid & 31;
    const int wm   = wid & 3;
    const int wn   = wid >> 2;
    const int bm   = blockIdx.y * 128;
    const int bn   = blockIdx.x * 128;

    const __half* tsrc[3] = {Ahi, Alo, Bh};
    const int tbase[3] = {bm, bm, bn};

    auto stage_load = [&](int c, int buf) {
#pragma unroll
        for (int t = 0; t < 3; t++) {
            const __half* src = tsrc[t];
            const int rb = tbase[t];
#pragma unroll
            for (int part = 0; part < 2; part++) {
                int idx = part * 512 + tid;
                int r   = idx >> 3;
                int ch  = idx & 7;
                const void* g = src + (size_t)(rb + r) * K + c * 64 + ch * 8;
                unsigned so = sb + buf * STAGE_SZ + t * TILE_SZ
                            + r * 128 + ((ch ^ (r & 7)) * 16);
                cp16(so, g);
            }
        }
    };

    float acc[2][4][4];
#pragma unroll
    for (int mi = 0; mi < 2; mi++)
#pragma unroll
        for (int ni = 0; ni < 4; ni++)
#pragma unroll
            for (int e = 0; e < 4; e++) acc[mi][ni][e] = 0.f;

    const int nK = K >> 6;
    stage_load(0, 0);
    cp_commit();

    for (int c = 0; c < nK; c++) {
        const int buf = c & 1;
        if (c + 1 < nK) {
            stage_load(c + 1, buf ^ 1);
            cp_commit();
            cp_wait1();
        } else {
            cp_wait0();
        }
        __syncthreads();

        const unsigned base = sb + buf * STAGE_SZ;
#pragma unroll
        for (int s = 0; s < 4; s++) {
            unsigned a_hi[2][4], a_lo[2][4];
#pragma unroll
            for (int mi = 0; mi < 2; mi++) {
                int r  = wm * 32 + mi * 16 + (lane & 15);
                int ch = 2 * s + (lane >> 4);
                unsigned ad = base + r * 128 + ((ch ^ (r & 7)) * 16);
                ldsm_x4(ad, a_hi[mi]);
                ldsm_x4(ad + TILE_SZ, a_lo[mi]);
            }
            unsigned b_h[2][4];
#pragma unroll
            for (int gi = 0; gi < 2; gi++) {
                int r  = wn * 32 + gi * 16 + (lane & 7) + ((lane >> 4) & 1) * 8;
                int ch = 2 * s + ((lane >> 3) & 1);
                unsigned ad = base + 2 * TILE_SZ + r * 128 + ((ch ^ (r & 7)) * 16);
                ldsm_x4(ad, b_h[gi]);
            }
#pragma unroll
            for (int mi = 0; mi < 2; mi++) {
#pragma unroll
                for (int ni = 0; ni < 4; ni++) {
                    const unsigned bh[2] = {b_h[ni >> 1][(ni & 1) * 2],
                                            b_h[ni >> 1][(ni & 1) * 2 + 1]};
                    mma_f16(acc[mi][ni], a_hi[mi], bh);
                    mma_f16(acc[mi][ni], a_lo[mi], bh);
                }
            }
        }
        __syncthreads();
    }

#pragma unroll
    for (int mi = 0; mi < 2; mi++) {
#pragma unroll
        for (int ni = 0; ni < 4; ni++) {
            int row = bm + wm * 32 + mi * 16 + (lane >> 2);
            int col = bn + wn * 32 + ni * 8 + (lane & 3) * 2;
            *(float2*)(C + (size_t)row * N + col) =
                make_float2(acc[mi][ni][0], acc[mi][ni][1]);
            *(float2*)(C + (size_t)(row + 8) * N + col) =
                make_float2(acc[mi][ni][2], acc[mi][ni][3]);
        }
    }
}

// ---------------------------------------------------------------------------
// RMSNorm + RoPE (+ q_gain); emits fp16 hi/lo to g_qh/g_ql, g_kh/g_kl
// ---------------------------------------------------------------------------
__global__ __launch_bounds__(256) void norm_rope_kernel(const float* __restrict__ qgain)
{
    const int gw   = (blockIdx.x * blockDim.x + threadIdx.x) >> 5;
    const int lane = threadIdx.x & 31;
    const int total = BN_ * TN_ * (HN + KVHN);
    if (gw >= total) return;

    const int head = gw % (HN + KVHN);
    const int row  = gw / (HN + KVHN);
    const int t    = row % TN_;

    const float* ptr;
    float gain = 1.f;
    if (head < HN) {
        ptr = g_q + (size_t)row * DIMN + head * HDN;
        gain = qgain[head];
    } else {
        ptr = g_k + (size_t)row * (KVHN * HDN) + (head - HN) * HDN;
    }

    float4 v = *(const float4*)(ptr + lane * 4);
    float ss = v.x * v.x + v.y * v.y + v.z * v.z + v.w * v.w;
#pragma unroll
    for (int o = 16; o; o >>= 1) ss += __shfl_xor_sync(0xffffffffu, ss, o);
    const float r = rsqrtf(ss * (1.f / 128.f) + EPS_RMS);
    v.x *= r; v.y *= r; v.z *= r; v.w *= r;

    float4 p;
    p.x = __shfl_xor_sync(0xffffffffu, v.x, 8);
    p.y = __shfl_xor_sync(0xffffffffu, v.y, 8);
    p.z = __shfl_xor_sync(0xffffffffu, v.z, 8);
    p.w = __shfl_xor_sync(0xffffffffu, v.w, 8);

    if (lane < 16) {
        const int base = (lane & 7) * 4;
        float* ve = &v.x;
        const float* pe = &p.x;
#pragma unroll
        for (int e = 0; e < 4; e++) {
            const int j = base + e;
            const float inv = powf(10000.f, -(float)j / 32.f);
            float s, c;
            sincosf((float)t * inv, &s, &c);
            if (lane < 8) ve[e] = ve[e] * c - pe[e] * s;
            else          ve[e] = ve[e] * c + pe[e] * s;
        }
    }
    v.x *= gain; v.y *= gain; v.z *= gain; v.w *= gain;

    float vv[4] = {v.x, v.y, v.z, v.w};
    __half h[4], l[4];
#pragma unroll
    for (int e = 0; e < 4; e++) {
        h[e] = __float2half_rn(vv[e]);
        l[e] = __float2half_rn(vv[e] - __half2float(h[e]));
    }
    if (head < HN) {
        size_t o = (size_t)row * DIMN + head * HDN + lane * 4;
        *(uint2*)(g_qh + o) = *(uint2*)h;
        *(uint2*)(g_ql + o) = *(uint2*)l;
    } else {
        size_t o = (size_t)row * (KVHN * HDN) + (head - HN) * HDN + lane * 4;
        *(uint2*)(g_kh + o) = *(uint2*)h;
        *(uint2*)(g_kl + o) = *(uint2*)l;
    }
}

// ---------------------------------------------------------------------------
// Tensor-core flash attention + v-orthogonalization.
// Block: 8 warps, 128 queries of one (b,h). Key tiles of 64, double-buffered.
// QK: split-3 fp16. PV: split-3 (P hi/lo x V hi/lo). O fp32 in registers.
// smem: Q hi/lo 64KB persistent + 2 x 64KB KV stages = 192KB.
// ---------------------------------------------------------------------------
#define ATT_SMEM 196608

__global__ __launch_bounds__(256) void attn_mma_kernel()
{
    extern __shared__ char smem[];
    const unsigned sb = smem_u32(smem);
    const int tid = threadIdx.x, wid = tid >> 5, lane = tid & 31;
    const int bh = blockIdx.y, b = bh / HN, h = bh % HN;
    const int kvh = h / (HN / KVHN);
    const int qb = (int)gridDim.x - 1 - (int)blockIdx.x;  // heavy blocks first
    const int t0 = qb * 128;

    // Stage Q hi/lo: 128 rows x 16 chunks (16B), XOR-swizzled
    for (int i = tid; i < 128 * 16; i += 256) {
        int r = i >> 4, ch = i & 15;
        size_t go = ((size_t)(b * TN_ + t0 + r)) * DIMN + h * HDN + ch * 8;
        unsigned so = sb + r * 256 + ((ch ^ (r & 7)) * 16);
        cp16(so, g_qh + go);
        cp16(so + 32768, g_ql + go);
    }
    cp_commit();

    const int ntiles = t0 / 64 + 2;
    auto kv_load = [&](int jt, int buf) {
        for (int i = tid; i < 64 * 16; i += 256) {
            int r = i >> 4, ch = i & 15;
            size_t go = ((size_t)(b * TN_ + jt * 64 + r)) * (KVHN * HDN) + kvh * HDN + ch * 8;
            unsigned so = sb + 65536 + buf * 65536 + r * 256 + ((ch ^ (r & 7)) * 16);
            cp16(so,         g_kh + go);
            cp16(so + 16384, g_kl + go);
            cp16(so + 32768, g_vh + go);
            cp16(so + 49152, g_vl + go);
        }
    };
    kv_load(0, 0);
    cp_commit();

    float O[16][4];
#pragma unroll
    for (int g = 0; g < 16; g++)
#pragma unroll
        for (int e = 0; e < 4; e++) O[g][e] = 0.f;
    float m0 = -INFINITY, m1 = -INFINITY, l0 = 0.f, l1 = 0.f;
    const int r0 = lane >> 2;
    const int tig2 = (lane & 3) * 2;
    const int qrow0 = t0 + wid * 16 + r0;     // rows qrow0, qrow0+8

    for (int jt = 0; jt < ntiles; jt++) {
        const int buf = jt & 1;
        if (jt + 1 < ntiles) { kv_load(jt + 1, buf ^ 1); cp_commit(); cp_wait1(); }
        else                 { cp_wait0(); }
        __syncthreads();

        const unsigned kvb = sb + 65536 + buf * 65536;
        const int j0 = jt * 64;

        // ---- S = Q K^T (split-3) ----
        float S[8][4];
#pragma unroll
        for (int nt = 0; nt < 8; nt++)
#pragma unroll
            for (int e = 0; e < 4; e++) S[nt][e] = 0.f;

#pragma unroll
        for (int kc = 0; kc < 8; kc++) {
            unsigned qh[4], ql[4];
            {
                int r  = wid * 16 + (lane & 15);
                int ch = 2 * kc + (lane >> 4);
                unsigned ad = sb + r * 256 + ((ch ^ (r & 7)) * 16);
                ldsm_x4(ad, qh);
                ldsm_x4(ad + 32768, ql);
            }
#pragma unroll
            for (int g = 0; g < 4; g++) {
                unsigned kh[4], kl[4];
                {
                    int r  = g * 16 + (lane & 7) + ((lane >> 4) & 1) * 8;
                    int ch = 2 * kc + ((lane >> 3) & 1);
                    unsigned ad = kvb + r * 256 + ((ch ^ (r & 7)) * 16);
                    ldsm_x4(ad, kh);
                    ldsm_x4(ad + 16384, kl);
                }
#pragma unroll
                for (int nn = 0; nn < 2; nn++) {
                    unsigned bh2[2] = {kh[nn * 2], kh[nn * 2 + 1]};
                    unsigned bl2[2] = {kl[nn * 2], kl[nn * 2 + 1]};
                    float* s = S[g * 2 + nn];
                    mma_f16(s, qh, bh2);
                    mma_f16(s, ql, bh2);
                    mma_f16(s, qh, bl2);
                }
            }
        }

        // ---- scale + causal mask ----
#pragma unroll
        for (int nt = 0; nt < 8; nt++) {
            int col = j0 + nt * 8 + tig2;
            S[nt][0] = (col     <= qrow0    ) ? S[nt][0] * QK_SCALE : -INFINITY;
            S[nt][1] = (col + 1 <= qrow0    ) ? S[nt][1] * QK_SCALE : -INFINITY;
            S[nt][2] = (col     <= qrow0 + 8) ? S[nt][2] * QK_SCALE : -INFINITY;
            S[nt][3] = (col + 1 <= qrow0 + 8) ? S[nt][3] * QK_SCALE : -INFINITY;
        }

        // ---- online softmax ----
        float mx0 = -INFINITY, mx1 = -INFINITY;
#pragma unroll
        for (int nt = 0; nt < 8; nt++) {
            mx0 = fmaxf(mx0, fmaxf(S[nt][0], S[nt][1]));
            mx1 = fmaxf(mx1, fmaxf(S[nt][2], S[nt][3]));
        }
        mx0 = fmaxf(mx0, __shfl_xor_sync(0xffffffffu, mx0, 1));
        mx0 = fmaxf(mx0, __shfl_xor_sync(0xffffffffu, mx0, 2));
        mx1 = fmaxf(mx1, __shfl_xor_sync(0xffffffffu, mx1, 1));
        mx1 = fmaxf(mx1, __shfl_xor_sync(0xffffffffu, mx1, 2));
        const float mn0 = fmaxf(m0, mx0), mn1 = fmaxf(m1, mx1);
        const float c0 = __expf(m0 - mn0), c1 = __expf(m1 - mn1);

        unsigned PH[4][4], PL[4][4];
        float sum0 = 0.f, sum1 = 0.f;
#pragma unroll
        for (int nt = 0; nt < 8; nt++) {
            float p0 = __expf(S[nt][0] - mn0);
            float p1 = __expf(S[nt][1] - mn0);
            float p2 = __expf(S[nt][2] - mn1);
            float p3 = __expf(S[nt][3] - mn1);
            sum0 += p0 + p1; sum1 += p2 + p3;
            __half h0 = __float2half_rn(p0), h1 = __float2half_rn(p1);
            __half h2 = __float2half_rn(p2), h3 = __float2half_rn(p3);
            __half u0 = __float2half_rn(p0 - __half2float(h0));
            __half u1 = __float2half_rn(p1 - __half2float(h1));
            __half u2 = __float2half_rn(p2 - __half2float(h2));
            __half u3 = __float2half_rn(p3 - __half2float(h3));
            int kc = nt >> 1, sl = (nt & 1) * 2;
            PH[kc][sl + 0] = packh(h0, h1);
            PH[kc][sl + 1] = packh(h2, h3);
            PL[kc][sl + 0] = packh(u0, u1);
            PL[kc][sl + 1] = packh(u2, u3);
        }
        sum0 += __shfl_xor_sync(0xffffffffu, sum0, 1);
        sum0 += __shfl_xor_sync(0xffffffffu, sum0, 2);
        sum1 += __shfl_xor_sync(0xffffffffu, sum1, 1);
        sum1 += __shfl_xor_sync(0xffffffffu, sum1, 2);
        l0 = l0 * c0 + sum0;
        l1 = l1 * c1 + sum1;
        m0 = mn0; m1 = mn1;
#pragma unroll
        for (int g = 0; g < 16; g++) {
            O[g][0] *= c0; O[g][1] *= c0; O[g][2] *= c1; O[g][3] *= c1;
        }

        // ---- O += P V (split-3) ----
#pragma unroll
        for (int kc = 0; kc < 4; kc++) {
#pragma unroll
            for (int g = 0; g < 8; g++) {
                unsigned vh[4], vl[4];
                {
                    int part = lane >> 3;
                    int key  = kc * 16 + (part & 1) * 8 + (lane & 7);
                    int ch   = g * 2 + (part >> 1);
                    unsigned ad = kvb + 32768 + key * 256 + ((ch ^ (key & 7)) * 16);
                    ldsm_x4_t(ad, vh);
                    ldsm_x4_t(ad + 16384, vl);
                }
#pragma unroll
                for (int nn = 0; nn < 2; nn++) {
                    unsigned bh2[2] = {vh[nn * 2], vh[nn * 2 + 1]};
                    unsigned bl2[2] = {vl[nn * 2], vl[nn * 2 + 1]};
                    float* o = O[g * 2 + nn];
                    mma_f16(o, PH[kc], bh2);
                    mma_f16(o, PL[kc], bh2);
                    mma_f16(o, PH[kc], bl2);
                }
            }
        }
        __syncthreads();
    }

    // ---- epilogue: normalize + v-orthogonalization + store ----
    const float inv0 = 1.f / l0, inv1 = 1.f / l1;
#pragma unroll
    for (int g = 0; g < 16; g++) {
        O[g][0] *= inv0; O[g][1] *= inv0; O[g][2] *= inv1; O[g][3] *= inv1;
    }

    const float* vb0 = g_v + ((size_t)(b * TN_ + qrow0)) * (KVHN * HDN) + kvh * HDN;
    const float* vb1 = vb0 + 8 * (KVHN * HDN);
    float nn0 = 0.f, nn1 = 0.f, dot0 = 0.f, dot1 = 0.f;
#pragma unroll
    for (int g = 0; g < 16; g++) {
        int col = g * 8 + tig2;
        float2 v0 = *(const float2*)(vb0 + col);
        float2 v1 = *(const float2*)(vb1 + col);
        nn0 += v0.x * v0.x + v0.y * v0.y;
        nn1 += v1.x * v1.x + v1.y * v1.y;
        dot0 += O[g][0] * v0.x + O[g][1] * v0.y;
        dot1 += O[g][2] * v1.x + O[g][3] * v1.y;
    }
    nn0 += __shfl_xor_sync(0xffffffffu, nn0, 1);
    nn0 += __shfl_xor_sync(0xffffffffu, nn0, 2);
    nn1 += __shfl_xor_sync(0xffffffffu, nn1, 1);
    nn1 += __shfl_xor_sync(0xffffffffu, nn1, 2);
    dot0 += __shfl_xor_sync(0xffffffffu, dot0, 1);
    dot0 += __shfl_xor_sync(0xffffffffu, dot0, 2);
    dot1 += __shfl_xor_sync(0xffffffffu, dot1, 1);
    dot1 += __shfl_xor_sync(0xffffffffu, dot1, 2);
    const float in0 = 1.f / fmaxf(sqrtf(nn0), EPS_NORM);
    const float in1 = 1.f / fmaxf(sqrtf(nn1), EPS_NORM);
    const float cf0 = dot0 * in0 * in0;
    const float cf1 = dot1 * in1 * in1;

    float* y0 = g_y + ((size_t)(b * TN_ + qrow0)) * DIMN + h * HDN;
    float* y1 = y0 + 8 * DIMN;
#pragma unroll
    for (int g = 0; g < 16; g++) {
        int col = g * 8 + tig2;
        float2 v0 = *(const float2*)(vb0 + col);
        float2 v1 = *(const float2*)(vb1 + col);
        *(float2*)(y0 + col) = make_float2(O[g][0] - cf0 * v0.x, O[g][1] - cf0 * v0.y);
        *(float2*)(y1 + col) = make_float2(O[g][2] - cf1 * v1.x, O[g][3] - cf1 * v1.y);
    }
}

// ---------------------------------------------------------------------------
// Launch
// ---------------------------------------------------------------------------
extern "C" void kernel_launch(void* const* d_in, const int* in_sizes, int n_in,
                              void* d_out, int out_size)
{
    const float* x     = (const float*)d_in[0];
    const float* Wq    = (const float*)d_in[1];
    const float* Wk    = (const float*)d_in[2];
    const float* Wv    = (const float*)d_in[3];
    const float* Wproj = (const float*)d_in[4];
    const float* qgain = (const float*)d_in[5];
    float* out = (float*)d_out;

    float *q_ptr, *k_ptr, *v_ptr, *y_ptr;
    cudaGetSymbolAddress((void**)&q_ptr, g_q);
    cudaGetSymbolAddress((void**)&k_ptr, g_k);
    cudaGetSymbolAddress((void**)&v_ptr, g_v);
    cudaGetSymbolAddress((void**)&y_ptr, g_y);
    __half *xhi, *xlo, *yhi, *ylo, *wq, *wk, *wv, *wp, *vh, *vl;
    cudaGetSymbolAddress((void**)&xhi, g_xhi); cudaGetSymbolAddress((void**)&xlo, g_xlo);
    cudaGetSymbolAddress((void**)&yhi, g_yhi); cudaGetSymbolAddress((void**)&ylo, g_ylo);
    cudaGetSymbolAddress((void**)&wq, g_wq);   cudaGetSymbolAddress((void**)&wk, g_wk);
    cudaGetSymbolAddress((void**)&wv, g_wv);   cudaGetSymbolAddress((void**)&wp, g_wp);
    cudaGetSymbolAddress((void**)&vh, g_vh);   cudaGetSymbolAddress((void**)&vl, g_vl);

    cudaFuncSetAttribute(gemm_mma_f16x2, cudaFuncAttributeMaxDynamicSharedMemorySize, GEMM_SMEM);
    cudaFuncSetAttribute(attn_mma_kernel, cudaFuncAttributeMaxDynamicSharedMemorySize, ATT_SMEM);

    const int M = BN_ * TN_;            // 8192
    const int NKV = KVHN * HDN;         // 512

    // Prep
    split2_kernel<<<(M * DIMN) / 1024, 256>>>(x, xhi, xlo, M * DIMN);
    round_all_kernel<<<10240, 256>>>(Wq, Wk, Wv, Wproj, wq, wk, wv, wp);

    // QKV projections
    gemm_mma_f16x2<<<dim3(DIMN / 128, M / 128), 512, GEMM_SMEM>>>(
        xhi, xlo, wq, q_ptr, M, DIMN, DIMN);
    gemm_mma_f16x2<<<dim3(NKV / 128, M / 128), 512, GEMM_SMEM>>>(
        xhi, xlo, wk, k_ptr, M, NKV, DIMN);
    gemm_mma_f16x2<<<dim3(NKV / 128, M / 128), 512, GEMM_SMEM>>>(
        xhi, xlo, wv, v_ptr, M, NKV, DIMN);

    // RMSNorm + RoPE -> fp16 hi/lo q,k ; split v -> fp16 hi/lo
    {
        const int total_warps = M * (HN + KVHN);
        const int blocks = (total_warps * 32 + 255) / 256;
        norm_rope_kernel<<<blocks, 256>>>(qgain);
    }
    split2_kernel<<<(M * NKV) / 1024, 256>>>(v_ptr, vh, vl, M * NKV);

    // Tensor-core flash attention
    attn_mma_kernel<<<dim3(TN_ / 128, BN_ * HN), 256, ATT_SMEM>>>();

    // Output projection
    split2_kernel<<<(M * DIMN) / 1024, 256>>>(y_ptr, yhi, ylo, M * DIMN);
    gemm_mma_f16x2<<<dim3(DIMN / 128, M / 128), 512, GEMM_SMEM>>>(
        yhi, ylo, wp, out, M, DIMN, DIMN);
}

// round 7
// speedup vs baseline: 6.8059x; 1.0256x over previous
#include <cuda_runtime.h>
#include <cuda_fp16.h>
#include <math.h>

// Problem constants
#define DIMN 2048
#define HN   16
#define KVHN 4
#define HDN  128
#define BN_  4
#define TN_  2048
#define QK_SCALE 0.08838834764831845f   // 128^-0.5
#define EPS_RMS  1e-6f
#define EPS_NORM 1e-12f

// ---------------------------------------------------------------------------
// Scratch (__device__ globals: allocation-free rule)
// ---------------------------------------------------------------------------
__device__ __align__(256) float g_q[(size_t)BN_ * TN_ * DIMN];
__device__ __align__(256) float g_k[(size_t)BN_ * TN_ * KVHN * HDN];
__device__ __align__(256) float g_v[(size_t)BN_ * TN_ * KVHN * HDN];

__device__ __align__(256) __half g_xhi[(size_t)BN_ * TN_ * DIMN];
__device__ __align__(256) __half g_xlo[(size_t)BN_ * TN_ * DIMN];
__device__ __align__(256) __half g_yhi[(size_t)BN_ * TN_ * DIMN];
__device__ __align__(256) __half g_ylo[(size_t)BN_ * TN_ * DIMN];
__device__ __align__(256) __half g_wq[(size_t)DIMN * DIMN];
__device__ __align__(256) __half g_wp[(size_t)DIMN * DIMN];
__device__ __align__(256) __half g_wk[(size_t)KVHN * HDN * DIMN];
__device__ __align__(256) __half g_wv[(size_t)KVHN * HDN * DIMN];

// fp16 operands for tensor-core attention
__device__ __align__(256) __half g_qh[(size_t)BN_ * TN_ * DIMN];
__device__ __align__(256) __half g_ql[(size_t)BN_ * TN_ * DIMN];
__device__ __align__(256) __half g_kh[(size_t)BN_ * TN_ * KVHN * HDN];
__device__ __align__(256) __half g_kl[(size_t)BN_ * TN_ * KVHN * HDN];
__device__ __align__(256) __half g_vh[(size_t)BN_ * TN_ * KVHN * HDN];
__device__ __align__(256) __half g_vl[(size_t)BN_ * TN_ * KVHN * HDN];

// ---------------------------------------------------------------------------
// Helpers
// ---------------------------------------------------------------------------
__device__ __forceinline__ unsigned smem_u32(const void* p) {
    unsigned a;
    asm("{ .reg .u64 t; cvta.to.shared.u64 t, %1; cvt.u32.u64 %0, t; }"
        : "=r"(a) : "l"(p));
    return a;
}
__device__ __forceinline__ void cp16(unsigned saddr, const void* gaddr) {
    asm volatile("cp.async.cg.shared.global [%0], [%1], 16;"
                 :: "r"(saddr), "l"(gaddr));
}
__device__ __forceinline__ void cp_commit() {
    asm volatile("cp.async.commit_group;" ::: "memory");
}
__device__ __forceinline__ void cp_wait1() {
    asm volatile("cp.async.wait_group 1;" ::: "memory");
}
__device__ __forceinline__ void cp_wait0() {
    asm volatile("cp.async.wait_group 0;" ::: "memory");
}
__device__ __forceinline__ void ldsm_x4(unsigned addr, unsigned* r) {
    asm volatile("ldmatrix.sync.aligned.m8n8.x4.shared.b16 {%0,%1,%2,%3}, [%4];"
                 : "=r"(r[0]), "=r"(r[1]), "=r"(r[2]), "=r"(r[3]) : "r"(addr));
}
__device__ __forceinline__ void ldsm_x4_t(unsigned addr, unsigned* r) {
    asm volatile("ldmatrix.sync.aligned.m8n8.x4.trans.shared.b16 {%0,%1,%2,%3}, [%4];"
                 : "=r"(r[0]), "=r"(r[1]), "=r"(r[2]), "=r"(r[3]) : "r"(addr));
}
__device__ __forceinline__ void mma_f16(float* d, const unsigned* a,
                                        const unsigned* b) {
    asm volatile(
        "mma.sync.aligned.m16n8k16.row.col.f32.f16.f16.f32 "
        "{%0,%1,%2,%3}, {%4,%5,%6,%7}, {%8,%9}, {%0,%1,%2,%3};"
        : "+f"(d[0]), "+f"(d[1]), "+f"(d[2]), "+f"(d[3])
        : "r"(a[0]), "r"(a[1]), "r"(a[2]), "r"(a[3]), "r"(b[0]), "r"(b[1]));
}
__device__ __forceinline__ unsigned packh(__half a, __half b) {
    __half2 t = __halves2half2(a, b);
    return *(unsigned*)&t;
}

// ---------------------------------------------------------------------------
// Prep kernels
// ---------------------------------------------------------------------------
__global__ __launch_bounds__(256) void split2_kernel(
    const float* __restrict__ s, __half* __restrict__ hi,
    __half* __restrict__ lo, int n)
{
    int i = (blockIdx.x * 256 + threadIdx.x) * 4;
    if (i >= n) return;
    float4 v = *(const float4*)(s + i);
    float vv[4] = {v.x, v.y, v.z, v.w};
    __half h[4], l[4];
#pragma unroll
    for (int e = 0; e < 4; e++) {
        h[e] = __float2half_rn(vv[e]);
        l[e] = __float2half_rn(vv[e] - __half2float(h[e]));
    }
    *(uint2*)(hi + i) = *(uint2*)h;
    *(uint2*)(lo + i) = *(uint2*)l;
}

__global__ __launch_bounds__(256) void round_all_kernel(
    const float* __restrict__ Wq, const float* __restrict__ Wk,
    const float* __restrict__ Wv, const float* __restrict__ Wp,
    __half* __restrict__ wq, __half* __restrict__ wk,
    __half* __restrict__ wv, __half* __restrict__ wp)
{
    int i = blockIdx.x * 256 + threadIdx.x;     // float4 index
    const float* s; __half* d; int off;
    if (i < 1048576)      { s = Wq; d = wq; off = i; }
    else if (i < 1310720) { s = Wk; d = wk; off = i - 1048576; }
    else if (i < 1572864) { s = Wv; d = wv; off = i - 1310720; }
    else                  { s = Wp; d = wp; off = i - 1572864; }
    float4 v = *(const float4*)(s + off * 4);
    __half h[4] = {__float2half(v.x), __float2half(v.y),
                   __float2half(v.z), __float2half(v.w)};
    *(uint2*)(d + off * 4) = *(uint2*)h;
}

// ---------------------------------------------------------------------------
// mma.sync fp16 split-2 GEMM: C[m,n] = sum_k A[m,k]*B[n,k]
// CTA 128(M) x 256(N) x BK64, 512 threads = 16 warps (4M x 4N), warp 32x64.
// Stage = {Ahi 16KB, Alo 16KB, B 32KB} = 64KB, double buffered = 128KB.
// ---------------------------------------------------------------------------
#define TILE_A2   16384          // 128 rows x 128B
#define TILE_B2   32768          // 256 rows x 128B
#define STAGE2    (2 * TILE_A2 + TILE_B2)   // 65536
#define GEMM_SMEM (2 * STAGE2)              // 131072

__global__ __launch_bounds__(512) void gemm_mma_f16x2(
    const __half* __restrict__ Ahi, const __half* __restrict__ Alo,
    const __half* __restrict__ Bh,
    float* __restrict__ C, int M, int N, int K)
{
    extern __shared__ char smem[];
    const unsigned sb = smem_u32(smem);
    const int tid  = threadIdx.x;
    const int wid  = tid >> 5;
    const int lane = tid & 31;
    const int wm   = wid & 3;      // M offset wm*32
    const int wn   = wid >> 2;     // N offset wn*64
    const int bm   = blockIdx.y * 128;
    const int bn   = blockIdx.x * 256;

    auto stage_load = [&](int c, int buf) {
        const unsigned st = sb + buf * STAGE2;
        // Ahi / Alo: 128 rows x 8 chunks
#pragma unroll
        for (int part = 0; part < 2; part++) {
            int idx = part * 512 + tid;          // 0..1023
            int r = idx >> 3, ch = idx & 7;
            size_t g = (size_t)(bm + r) * K + c * 64 + ch * 8;
            unsigned so = st + r * 128 + ((ch ^ (r & 7)) * 16);
            cp16(so, Ahi + g);
            cp16(so + TILE_A2, Alo + g);
        }
        // B: 256 rows x 8 chunks
#pragma unroll
        for (int part = 0; part < 4; part++) {
            int idx = part * 512 + tid;          // 0..2047
            int r = idx >> 3, ch = idx & 7;
            size_t g = (size_t)(bn + r) * K + c * 64 + ch * 8;
            unsigned so = st + 2 * TILE_A2 + r * 128 + ((ch ^ (r & 7)) * 16);
            cp16(so, Bh + g);
        }
    };

    float acc[2][8][4];
#pragma unroll
    for (int mi = 0; mi < 2; mi++)
#pragma unroll
        for (int ni = 0; ni < 8; ni++)
#pragma unroll
            for (int e = 0; e < 4; e++) acc[mi][ni][e] = 0.f;

    const int nK = K >> 6;
    stage_load(0, 0);
    cp_commit();

    for (int c = 0; c < nK; c++) {
        const int buf = c & 1;
        if (c + 1 < nK) {
            stage_load(c + 1, buf ^ 1);
            cp_commit();
            cp_wait1();
        } else {
            cp_wait0();
        }
        __syncthreads();

        const unsigned base = sb + buf * STAGE2;
#pragma unroll
        for (int s = 0; s < 4; s++) {
            unsigned a_hi[2][4], a_lo[2][4];
#pragma unroll
            for (int mi = 0; mi < 2; mi++) {
                int r  = wm * 32 + mi * 16 + (lane & 15);
                int ch = 2 * s + (lane >> 4);
                unsigned ad = base + r * 128 + ((ch ^ (r & 7)) * 16);
                ldsm_x4(ad, a_hi[mi]);
                ldsm_x4(ad + TILE_A2, a_lo[mi]);
            }
            unsigned b_h[4][4];
#pragma unroll
            for (int gi = 0; gi < 4; gi++) {
                int r  = wn * 64 + gi * 16 + (lane & 7) + ((lane >> 4) & 1) * 8;
                int ch = 2 * s + ((lane >> 3) & 1);
                unsigned ad = base + 2 * TILE_A2 + r * 128 + ((ch ^ (r & 7)) * 16);
                ldsm_x4(ad, b_h[gi]);
            }
#pragma unroll
            for (int mi = 0; mi < 2; mi++) {
#pragma unroll
                for (int ni = 0; ni < 8; ni++) {
                    const unsigned bh[2] = {b_h[ni >> 1][(ni & 1) * 2],
                                            b_h[ni >> 1][(ni & 1) * 2 + 1]};
                    mma_f16(acc[mi][ni], a_hi[mi], bh);
                    mma_f16(acc[mi][ni], a_lo[mi], bh);
                }
            }
        }
        __syncthreads();
    }

#pragma unroll
    for (int mi = 0; mi < 2; mi++) {
#pragma unroll
        for (int ni = 0; ni < 8; ni++) {
            int row = bm + wm * 32 + mi * 16 + (lane >> 2);
            int col = bn + wn * 64 + ni * 8 + (lane & 3) * 2;
            *(float2*)(C + (size_t)row * N + col) =
                make_float2(acc[mi][ni][0], acc[mi][ni][1]);
            *(float2*)(C + (size_t)(row + 8) * N + col) =
                make_float2(acc[mi][ni][2], acc[mi][ni][3]);
        }
    }
}

// ---------------------------------------------------------------------------
// RMSNorm + RoPE (+ q_gain); emits fp16 hi/lo to g_qh/g_ql, g_kh/g_kl
// ---------------------------------------------------------------------------
__global__ __launch_bounds__(256) void norm_rope_kernel(const float* __restrict__ qgain)
{
    const int gw   = (blockIdx.x * blockDim.x + threadIdx.x) >> 5;
    const int lane = threadIdx.x & 31;
    const int total = BN_ * TN_ * (HN + KVHN);
    if (gw >= total) return;

    const int head = gw % (HN + KVHN);
    const int row  = gw / (HN + KVHN);
    const int t    = row % TN_;

    const float* ptr;
    float gain = 1.f;
    if (head < HN) {
        ptr = g_q + (size_t)row * DIMN + head * HDN;
        gain = qgain[head];
    } else {
        ptr = g_k + (size_t)row * (KVHN * HDN) + (head - HN) * HDN;
    }

    float4 v = *(const float4*)(ptr + lane * 4);
    float ss = v.x * v.x + v.y * v.y + v.z * v.z + v.w * v.w;
#pragma unroll
    for (int o = 16; o; o >>= 1) ss += __shfl_xor_sync(0xffffffffu, ss, o);
    const float r = rsqrtf(ss * (1.f / 128.f) + EPS_RMS);
    v.x *= r; v.y *= r; v.z *= r; v.w *= r;

    float4 p;
    p.x = __shfl_xor_sync(0xffffffffu, v.x, 8);
    p.y = __shfl_xor_sync(0xffffffffu, v.y, 8);
    p.z = __shfl_xor_sync(0xffffffffu, v.z, 8);
    p.w = __shfl_xor_sync(0xffffffffu, v.w, 8);

    if (lane < 16) {
        const int base = (lane & 7) * 4;
        float* ve = &v.x;
        const float* pe = &p.x;
#pragma unroll
        for (int e = 0; e < 4; e++) {
            const int j = base + e;
            const float inv = powf(10000.f, -(float)j / 32.f);
            float s, c;
            sincosf((float)t * inv, &s, &c);
            if (lane < 8) ve[e] = ve[e] * c - pe[e] * s;
            else          ve[e] = ve[e] * c + pe[e] * s;
        }
    }
    v.x *= gain; v.y *= gain; v.z *= gain; v.w *= gain;

    float vv[4] = {v.x, v.y, v.z, v.w};
    __half h[4], l[4];
#pragma unroll
    for (int e = 0; e < 4; e++) {
        h[e] = __float2half_rn(vv[e]);
        l[e] = __float2half_rn(vv[e] - __half2float(h[e]));
    }
    if (head < HN) {
        size_t o = (size_t)row * DIMN + head * HDN + lane * 4;
        *(uint2*)(g_qh + o) = *(uint2*)h;
        *(uint2*)(g_ql + o) = *(uint2*)l;
    } else {
        size_t o = (size_t)row * (KVHN * HDN) + (head - HN) * HDN + lane * 4;
        *(uint2*)(g_kh + o) = *(uint2*)h;
        *(uint2*)(g_kl + o) = *(uint2*)l;
    }
}

// ---------------------------------------------------------------------------
// Tensor-core flash attention + v-orthogonalization.
// Emits yhi/ylo fp16 directly (proj GEMM input) — no fp32 y round-trip.
// ---------------------------------------------------------------------------
#define ATT_SMEM 196608

__global__ __launch_bounds__(256) void attn_mma_kernel()
{
    extern __shared__ char smem[];
    const unsigned sb = smem_u32(smem);
    const int tid = threadIdx.x, wid = tid >> 5, lane = tid & 31;
    const int bh = blockIdx.y, b = bh / HN, h = bh % HN;
    const int kvh = h / (HN / KVHN);
    const int qb = (int)gridDim.x - 1 - (int)blockIdx.x;  // heavy blocks first
    const int t0 = qb * 128;

    // Stage Q hi/lo: 128 rows x 16 chunks (16B), XOR-swizzled
    for (int i = tid; i < 128 * 16; i += 256) {
        int r = i >> 4, ch = i & 15;
        size_t go = ((size_t)(b * TN_ + t0 + r)) * DIMN + h * HDN + ch * 8;
        unsigned so = sb + r * 256 + ((ch ^ (r & 7)) * 16);
        cp16(so, g_qh + go);
        cp16(so + 32768, g_ql + go);
    }
    cp_commit();

    const int ntiles = t0 / 64 + 2;
    auto kv_load = [&](int jt, int buf) {
        for (int i = tid; i < 64 * 16; i += 256) {
            int r = i >> 4, ch = i & 15;
            size_t go = ((size_t)(b * TN_ + jt * 64 + r)) * (KVHN * HDN) + kvh * HDN + ch * 8;
            unsigned so = sb + 65536 + buf * 65536 + r * 256 + ((ch ^ (r & 7)) * 16);
            cp16(so,         g_kh + go);
            cp16(so + 16384, g_kl + go);
            cp16(so + 32768, g_vh + go);
            cp16(so + 49152, g_vl + go);
        }
    };
    kv_load(0, 0);
    cp_commit();

    float O[16][4];
#pragma unroll
    for (int g = 0; g < 16; g++)
#pragma unroll
        for (int e = 0; e < 4; e++) O[g][e] = 0.f;
    float m0 = -INFINITY, m1 = -INFINITY, l0 = 0.f, l1 = 0.f;
    const int r0 = lane >> 2;
    const int tig2 = (lane & 3) * 2;
    const int qrow0 = t0 + wid * 16 + r0;

    for (int jt = 0; jt < ntiles; jt++) {
        const int buf = jt & 1;
        if (jt + 1 < ntiles) { kv_load(jt + 1, buf ^ 1); cp_commit(); cp_wait1(); }
        else                 { cp_wait0(); }
        __syncthreads();

        const unsigned kvb = sb + 65536 + buf * 65536;
        const int j0 = jt * 64;

        // ---- S = Q K^T (split-3) ----
        float S[8][4];
#pragma unroll
        for (int nt = 0; nt < 8; nt++)
#pragma unroll
            for (int e = 0; e < 4; e++) S[nt][e] = 0.f;

#pragma unroll
        for (int kc = 0; kc < 8; kc++) {
            unsigned qh[4], ql[4];
            {
                int r  = wid * 16 + (lane & 15);
                int ch = 2 * kc + (lane >> 4);
                unsigned ad = sb + r * 256 + ((ch ^ (r & 7)) * 16);
                ldsm_x4(ad, qh);
                ldsm_x4(ad + 32768, ql);
            }
#pragma unroll
            for (int g = 0; g < 4; g++) {
                unsigned kh[4], kl[4];
                {
                    int r  = g * 16 + (lane & 7) + ((lane >> 4) & 1) * 8;
                    int ch = 2 * kc + ((lane >> 3) & 1);
                    unsigned ad = kvb + r * 256 + ((ch ^ (r & 7)) * 16);
                    ldsm_x4(ad, kh);
                    ldsm_x4(ad + 16384, kl);
                }
#pragma unroll
                for (int nn = 0; nn < 2; nn++) {
                    unsigned bh2[2] = {kh[nn * 2], kh[nn * 2 + 1]};
                    unsigned bl2[2] = {kl[nn * 2], kl[nn * 2 + 1]};
                    float* s = S[g * 2 + nn];
                    mma_f16(s, qh, bh2);
                    mma_f16(s, ql, bh2);
                    mma_f16(s, qh, bl2);
                }
            }
        }

        // ---- scale + causal mask ----
#pragma unroll
        for (int nt = 0; nt < 8; nt++) {
            int col = j0 + nt * 8 + tig2;
            S[nt][0] = (col     <= qrow0    ) ? S[nt][0] * QK_SCALE : -INFINITY;
            S[nt][1] = (col + 1 <= qrow0    ) ? S[nt][1] * QK_SCALE : -INFINITY;
            S[nt][2] = (col     <= qrow0 + 8) ? S[nt][2] * QK_SCALE : -INFINITY;
            S[nt][3] = (col + 1 <= qrow0 + 8) ? S[nt][3] * QK_SCALE : -INFINITY;
        }

        // ---- online softmax ----
        float mx0 = -INFINITY, mx1 = -INFINITY;
#pragma unroll
        for (int nt = 0; nt < 8; nt++) {
            mx0 = fmaxf(mx0, fmaxf(S[nt][0], S[nt][1]));
            mx1 = fmaxf(mx1, fmaxf(S[nt][2], S[nt][3]));
        }
        mx0 = fmaxf(mx0, __shfl_xor_sync(0xffffffffu, mx0, 1));
        mx0 = fmaxf(mx0, __shfl_xor_sync(0xffffffffu, mx0, 2));
        mx1 = fmaxf(mx1, __shfl_xor_sync(0xffffffffu, mx1, 1));
        mx1 = fmaxf(mx1, __shfl_xor_sync(0xffffffffu, mx1, 2));
        const float mn0 = fmaxf(m0, mx0), mn1 = fmaxf(m1, mx1);
        const float c0 = __expf(m0 - mn0), c1 = __expf(m1 - mn1);

        unsigned PH[4][4], PL[4][4];
        float sum0 = 0.f, sum1 = 0.f;
#pragma unroll
        for (int nt = 0; nt < 8; nt++) {
            float p0 = __expf(S[nt][0] - mn0);
            float p1 = __expf(S[nt][1] - mn0);
            float p2 = __expf(S[nt][2] - mn1);
            float p3 = __expf(S[nt][3] - mn1);
            sum0 += p0 + p1; sum1 += p2 + p3;
            __half h0 = __float2half_rn(p0), h1 = __float2half_rn(p1);
            __half h2 = __float2half_rn(p2), h3 = __float2half_rn(p3);
            __half u0 = __float2half_rn(p0 - __half2float(h0));
            __half u1 = __float2half_rn(p1 - __half2float(h1));
            __half u2 = __float2half_rn(p2 - __half2float(h2));
            __half u3 = __float2half_rn(p3 - __half2float(h3));
            int kc = nt >> 1, sl = (nt & 1) * 2;
            PH[kc][sl + 0] = packh(h0, h1);
            PH[kc][sl + 1] = packh(h2, h3);
            PL[kc][sl + 0] = packh(u0, u1);
            PL[kc][sl + 1] = packh(u2, u3);
        }
        sum0 += __shfl_xor_sync(0xffffffffu, sum0, 1);
        sum0 += __shfl_xor_sync(0xffffffffu, sum0, 2);
        sum1 += __shfl_xor_sync(0xffffffffu, sum1, 1);
        sum1 += __shfl_xor_sync(0xffffffffu, sum1, 2);
        l0 = l0 * c0 + sum0;
        l1 = l1 * c1 + sum1;
        m0 = mn0; m1 = mn1;
#pragma unroll
        for (int g = 0; g < 16; g++) {
            O[g][0] *= c0; O[g][1] *= c0; O[g][2] *= c1; O[g][3] *= c1;
        }

        // ---- O += P V (split-3) ----
#pragma unroll
        for (int kc = 0; kc < 4; kc++) {
#pragma unroll
            for (int g = 0; g < 8; g++) {
                unsigned vh[4], vl[4];
                {
                    int part = lane >> 3;
                    int key  = kc * 16 + (part & 1) * 8 + (lane & 7);
                    int ch   = g * 2 + (part >> 1);
                    unsigned ad = kvb + 32768 + key * 256 + ((ch ^ (key & 7)) * 16);
                    ldsm_x4_t(ad, vh);
                    ldsm_x4_t(ad + 16384, vl);
                }
#pragma unroll
                for (int nn = 0; nn < 2; nn++) {
                    unsigned bh2[2] = {vh[nn * 2], vh[nn * 2 + 1]};
                    unsigned bl2[2] = {vl[nn * 2], vl[nn * 2 + 1]};
                    float* o = O[g * 2 + nn];
                    mma_f16(o, PH[kc], bh2);
                    mma_f16(o, PL[kc], bh2);
                    mma_f16(o, PH[kc], bl2);
                }
            }
        }
        __syncthreads();
    }

    // ---- epilogue: normalize + v-orthogonalization + fp16 hi/lo store ----
    const float inv0 = 1.f / l0, inv1 = 1.f / l1;
#pragma unroll
    for (int g = 0; g < 16; g++) {
        O[g][0] *= inv0; O[g][1] *= inv0; O[g][2] *= inv1; O[g][3] *= inv1;
    }

    const float* vb0 = g_v + ((size_t)(b * TN_ + qrow0)) * (KVHN * HDN) + kvh * HDN;
    const float* vb1 = vb0 + 8 * (KVHN * HDN);
    float nn0 = 0.f, nn1 = 0.f, dot0 = 0.f, dot1 = 0.f;
#pragma unroll
    for (int g = 0; g < 16; g++) {
        int col = g * 8 + tig2;
        float2 v0 = *(const float2*)(vb0 + col);
        float2 v1 = *(const float2*)(vb1 + col);
        nn0 += v0.x * v0.x + v0.y * v0.y;
        nn1 += v1.x * v1.x + v1.y * v1.y;
        dot0 += O[g][0] * v0.x + O[g][1] * v0.y;
        dot1 += O[g][2] * v1.x + O[g][3] * v1.y;
    }
    nn0 += __shfl_xor_sync(0xffffffffu, nn0, 1);
    nn0 += __shfl_xor_sync(0xffffffffu, nn0, 2);
    nn1 += __shfl_xor_sync(0xffffffffu, nn1, 1);
    nn1 += __shfl_xor_sync(0xffffffffu, nn1, 2);
    dot0 += __shfl_xor_sync(0xffffffffu, dot0, 1);
    dot0 += __shfl_xor_sync(0xffffffffu, dot0, 2);
    dot1 += __shfl_xor_sync(0xffffffffu, dot1, 1);
    dot1 += __shfl_xor_sync(0xffffffffu, dot1, 2);
    const float in0 = 1.f / fmaxf(sqrtf(nn0), EPS_NORM);
    const float in1 = 1.f / fmaxf(sqrtf(nn1), EPS_NORM);
    const float cf0 = dot0 * in0 * in0;
    const float cf1 = dot1 * in1 * in1;

    const size_t y0 = ((size_t)(b * TN_ + qrow0)) * DIMN + h * HDN;
    const size_t y1 = y0 + 8 * DIMN;
#pragma unroll
    for (int g = 0; g < 16; g++) {
        int col = g * 8 + tig2;
        float2 v0 = *(const float2*)(vb0 + col);
        float2 v1 = *(const float2*)(vb1 + col);
        float o00 = O[g][0] - cf0 * v0.x, o01 = O[g][1] - cf0 * v0.y;
        float o10 = O[g][2] - cf1 * v1.x, o11 = O[g][3] - cf1 * v1.y;
        __half h00 = __float2half_rn(o00), h01 = __float2half_rn(o01);
        __half h10 = __float2half_rn(o10), h11 = __float2half_rn(o11);
        __half l00 = __float2half_rn(o00 - __half2float(h00));
        __half l01 = __float2half_rn(o01 - __half2float(h01));
        __half l10 = __float2half_rn(o10 - __half2float(h10));
        __half l11 = __float2half_rn(o11 - __half2float(h11));
        *(__half2*)(g_yhi + y0 + col) = __halves2half2(h00, h01);
        *(__half2*)(g_ylo + y0 + col) = __halves2half2(l00, l01);
        *(__half2*)(g_yhi + y1 + col) = __halves2half2(h10, h11);
        *(__half2*)(g_ylo + y1 + col) = __halves2half2(l10, l11);
    }
}

// ---------------------------------------------------------------------------
// Launch
// ---------------------------------------------------------------------------
extern "C" void kernel_launch(void* const* d_in, const int* in_sizes, int n_in,
                              void* d_out, int out_size)
{
    const float* x     = (const float*)d_in[0];
    const float* Wq    = (const float*)d_in[1];
    const float* Wk    = (const float*)d_in[2];
    const float* Wv    = (const float*)d_in[3];
    const float* Wproj = (const float*)d_in[4];
    const float* qgain = (const float*)d_in[5];
    float* out = (float*)d_out;

    float *q_ptr, *k_ptr, *v_ptr;
    cudaGetSymbolAddress((void**)&q_ptr, g_q);
    cudaGetSymbolAddress((void**)&k_ptr, g_k);
    cudaGetSymbolAddress((void**)&v_ptr, g_v);
    __half *xhi, *xlo, *yhi, *ylo, *wq, *wk, *wv, *wp, *vh, *vl;
    cudaGetSymbolAddress((void**)&xhi, g_xhi); cudaGetSymbolAddress((void**)&xlo, g_xlo);
    cudaGetSymbolAddress((void**)&yhi, g_yhi); cudaGetSymbolAddress((void**)&ylo, g_ylo);
    cudaGetSymbolAddress((void**)&wq, g_wq);   cudaGetSymbolAddress((void**)&wk, g_wk);
    cudaGetSymbolAddress((void**)&wv, g_wv);   cudaGetSymbolAddress((void**)&wp, g_wp);
    cudaGetSymbolAddress((void**)&vh, g_vh);   cudaGetSymbolAddress((void**)&vl, g_vl);

    cudaFuncSetAttribute(gemm_mma_f16x2, cudaFuncAttributeMaxDynamicSharedMemorySize, GEMM_SMEM);
    cudaFuncSetAttribute(attn_mma_kernel, cudaFuncAttributeMaxDynamicSharedMemorySize, ATT_SMEM);

    const int M = BN_ * TN_;            // 8192
    const int NKV = KVHN * HDN;         // 512

    // Prep
    split2_kernel<<<(M * DIMN) / 1024, 256>>>(x, xhi, xlo, M * DIMN);
    round_all_kernel<<<10240, 256>>>(Wq, Wk, Wv, Wproj, wq, wk, wv, wp);

    // QKV projections (CTA tile 128x256)
    gemm_mma_f16x2<<<dim3(DIMN / 256, M / 128), 512, GEMM_SMEM>>>(
        xhi, xlo, wq, q_ptr, M, DIMN, DIMN);
    gemm_mma_f16x2<<<dim3(NKV / 256, M / 128), 512, GEMM_SMEM>>>(
        xhi, xlo, wk, k_ptr, M, NKV, DIMN);
    gemm_mma_f16x2<<<dim3(NKV / 256, M / 128), 512, GEMM_SMEM>>>(
        xhi, xlo, wv, v_ptr, M, NKV, DIMN);

    // RMSNorm + RoPE -> fp16 hi/lo q,k ; split v -> fp16 hi/lo
    {
        const int total_warps = M * (HN + KVHN);
        const int blocks = (total_warps * 32 + 255) / 256;
        norm_rope_kernel<<<blocks, 256>>>(qgain);
    }
    split2_kernel<<<(M * NKV) / 1024, 256>>>(v_ptr, vh, vl, M * NKV);

    // Tensor-core flash attention (emits yhi/ylo)
    attn_mma_kernel<<<dim3(TN_ / 128, BN_ * HN), 256, ATT_SMEM>>>();

    // Output projection
    gemm_mma_f16x2<<<dim3(DIMN / 256, M / 128), 512, GEMM_SMEM>>>(
        yhi, ylo, wp, out, M, DIMN, DIMN);
}